// round 1
// baseline (speedup 1.0000x reference)
#include <cuda_runtime.h>
#include <cuda_bf16.h>
#include <math.h>

// Problem constants (fixed shapes from setup_inputs)
#define BATCH 32
#define SEQ   864
#define CDIM  768
#define NHEAD 12
#define HDIM  64
#define TT    288   // 2*t_h*t_w
#define TS    576   // s_h*s_w
#define MT    72    // 2*((t_h+1)//2)^2
#define MS    144   // s_h*s_w/4
#define QKVN  2304  // 3*CDIM
#define MROWS (BATCH*SEQ)   // 27648

// Scratch (allocation-free: __device__ globals)
__device__ float g_qkv[(size_t)MROWS * QKVN];   // (B*N, 3C)
__device__ float g_y[(size_t)MROWS * CDIM];     // attention output (B*N, C)

// ---------------------------------------------------------------------------
// Classic 128x128x8 SGEMM, 256 threads, 8x8 microtile, float4 global loads.
// C = A(MxK) @ B(KxN) [+ bias].  All dims divisible by tile sizes here.
// ---------------------------------------------------------------------------
#define BM 128
#define BN 128
#define BK 8
#define TM 8
#define TN 8

__global__ __launch_bounds__(256) void sgemm_kernel(
    const float* __restrict__ A, const float* __restrict__ B,
    float* __restrict__ C, const float* __restrict__ bias,
    int M, int N, int K)
{
    __shared__ float As[BK][BM];
    __shared__ float Bs[BK][BN];

    const int tid = threadIdx.x;
    const int bm = blockIdx.y * BM;
    const int bn = blockIdx.x * BN;
    const int ty = tid >> 4;          // 0..15
    const int tx = tid & 15;          // 0..15

    const int arow = tid >> 1;        // 0..127
    const int acol = (tid & 1) * 4;   // 0 or 4
    const int brow = tid >> 5;        // 0..7
    const int bcol = (tid & 31) * 4;  // 0..124

    float acc[TM][TN];
#pragma unroll
    for (int i = 0; i < TM; i++)
#pragma unroll
        for (int j = 0; j < TN; j++) acc[i][j] = 0.f;

    for (int k0 = 0; k0 < K; k0 += BK) {
        float4 a4 = *(const float4*)&A[(size_t)(bm + arow) * K + k0 + acol];
        As[acol + 0][arow] = a4.x;
        As[acol + 1][arow] = a4.y;
        As[acol + 2][arow] = a4.z;
        As[acol + 3][arow] = a4.w;
        float4 b4 = *(const float4*)&B[(size_t)(k0 + brow) * N + bn + bcol];
        *(float4*)&Bs[brow][bcol] = b4;
        __syncthreads();

#pragma unroll
        for (int kk = 0; kk < BK; kk++) {
            float ar[TM], br[TN];
#pragma unroll
            for (int i = 0; i < TM; i++) ar[i] = As[kk][ty * TM + i];
#pragma unroll
            for (int j = 0; j < TN; j++) br[j] = Bs[kk][tx * TN + j];
#pragma unroll
            for (int i = 0; i < TM; i++)
#pragma unroll
                for (int j = 0; j < TN; j++)
                    acc[i][j] = fmaf(ar[i], br[j], acc[i][j]);
        }
        __syncthreads();
    }

#pragma unroll
    for (int i = 0; i < TM; i++) {
        const int row = bm + ty * TM + i;
#pragma unroll
        for (int j = 0; j < TN; j += 4) {
            const int col = bn + tx * TN + j;
            float4 v;
            v.x = acc[i][j + 0];
            v.y = acc[i][j + 1];
            v.z = acc[i][j + 2];
            v.w = acc[i][j + 3];
            if (bias) {
                v.x += bias[col + 0];
                v.y += bias[col + 1];
                v.z += bias[col + 2];
                v.w += bias[col + 3];
            }
            *(float4*)&C[(size_t)row * N + col] = v;
        }
    }
}

// ---------------------------------------------------------------------------
// Flash-style attention. One block handles 96 queries of one (b, h).
// K/V tile staged in dynamic SMEM; each thread owns one query (online softmax).
//   pattern A: queries [0,288)   attend keys [72,216)  (nk=144)
//   pattern B: queries [288,864) attend keys [0,72)    (nk=72)
// qkv layout: (B*N, 2304); q at col h*64, k at 768+h*64, v at 1536+h*64.
// y layout: (B*N, 768), col h*64.
// ---------------------------------------------------------------------------
#define QPB 96

__global__ __launch_bounds__(QPB) void attn_kernel(
    const float* __restrict__ qkv, float* __restrict__ y,
    int n0q, int nqblocks, int n0k, int nk)
{
    extern __shared__ float sm[];
    float* sK = sm;
    float* sV = sm + (size_t)nk * HDIM;

    const int qb = blockIdx.x % nqblocks;
    const int bh = blockIdx.x / nqblocks;
    const int b = bh / NHEAD;
    const int h = bh % NHEAD;

    const float* base = qkv + (size_t)b * SEQ * QKVN + h * HDIM;

    // Cooperative K/V load (row stride QKVN, 64 contiguous floats per row)
    for (int idx = threadIdx.x; idx < nk * HDIM; idx += QPB) {
        const int r = idx >> 6;
        const int c = idx & 63;
        sK[idx] = base[(size_t)(n0k + r) * QKVN + CDIM + c];
        sV[idx] = base[(size_t)(n0k + r) * QKVN + 2 * CDIM + c];
    }
    __syncthreads();

    const int iq = qb * QPB + threadIdx.x;
    const float* qp = base + (size_t)(n0q + iq) * QKVN;

    float q[HDIM], o[HDIM];
#pragma unroll
    for (int i = 0; i < HDIM; i += 4) {
        float4 t = *(const float4*)&qp[i];
        q[i + 0] = t.x; q[i + 1] = t.y; q[i + 2] = t.z; q[i + 3] = t.w;
    }
#pragma unroll
    for (int i = 0; i < HDIM; i++) o[i] = 0.f;

    float m = -1e30f, l = 0.f;
    const float scale = 0.125f;  // 64^-0.5

    for (int j = 0; j < nk; j++) {
        const float* kj = &sK[j * HDIM];
        float s = 0.f;
#pragma unroll
        for (int i = 0; i < HDIM; i += 4) {
            float4 kv = *(const float4*)&kj[i];
            s = fmaf(q[i + 0], kv.x, s);
            s = fmaf(q[i + 1], kv.y, s);
            s = fmaf(q[i + 2], kv.z, s);
            s = fmaf(q[i + 3], kv.w, s);
        }
        s *= scale;
        const float nm = fmaxf(m, s);
        const float corr = __expf(m - nm);
        const float p = __expf(s - nm);
        l = l * corr + p;
        const float* vj = &sV[j * HDIM];
#pragma unroll
        for (int i = 0; i < HDIM; i += 4) {
            float4 vv = *(const float4*)&vj[i];
            o[i + 0] = fmaf(o[i + 0], corr, p * vv.x);
            o[i + 1] = fmaf(o[i + 1], corr, p * vv.y);
            o[i + 2] = fmaf(o[i + 2], corr, p * vv.z);
            o[i + 3] = fmaf(o[i + 3], corr, p * vv.w);
        }
        m = nm;
    }

    const float inv = 1.f / l;
    float* yp = y + (size_t)(b * SEQ + n0q + iq) * CDIM + h * HDIM;
#pragma unroll
    for (int i = 0; i < HDIM; i += 4) {
        float4 v;
        v.x = o[i + 0] * inv;
        v.y = o[i + 1] * inv;
        v.z = o[i + 2] * inv;
        v.w = o[i + 3] * inv;
        *(float4*)&yp[i] = v;
    }
}

// ---------------------------------------------------------------------------
// Launch: GEMM1 -> attn A -> attn B -> GEMM2(+bias)
// ---------------------------------------------------------------------------
extern "C" void kernel_launch(void* const* d_in, const int* in_sizes, int n_in,
                              void* d_out, int out_size)
{
    const float* x     = (const float*)d_in[0];
    const float* Wqkv  = (const float*)d_in[1];
    const float* Wproj = (const float*)d_in[2];
    const float* bproj = (const float*)d_in[3];
    float* out = (float*)d_out;

    // Scratch pointers from __device__ globals (no allocation).
    void* qkv_ptr = nullptr;
    void* y_ptr = nullptr;
    cudaGetSymbolAddress(&qkv_ptr, g_qkv);
    cudaGetSymbolAddress(&y_ptr, g_y);
    float* qkv = (float*)qkv_ptr;
    float* yv = (float*)y_ptr;

    // Pattern A needs 2*144*64*4 = 73728 B dynamic smem (> 48KB default).
    // Attribute set is idempotent and capture-safe.
    const int smemA = 2 * MS * HDIM * (int)sizeof(float);
    const int smemB = 2 * MT * HDIM * (int)sizeof(float);
    cudaFuncSetAttribute(attn_kernel,
                         cudaFuncAttributeMaxDynamicSharedMemorySize, smemA);

    // GEMM1: qkv = x @ W_qkv   (27648 x 2304 x 768)
    {
        dim3 grid(QKVN / BN, MROWS / BM);
        sgemm_kernel<<<grid, 256>>>(x, Wqkv, qkv, nullptr, MROWS, QKVN, CDIM);
    }

    // Attention pattern A: q[0:288] x k_s/v_s (keys 72..215)
    attn_kernel<<<BATCH * NHEAD * (TT / QPB), QPB, smemA>>>(
        qkv, yv, /*n0q=*/0, /*nqblocks=*/TT / QPB, /*n0k=*/MT, /*nk=*/MS);

    // Attention pattern B: q[288:864] x k_t/v_t (keys 0..71)
    attn_kernel<<<BATCH * NHEAD * (TS / QPB), QPB, smemB>>>(
        qkv, yv, /*n0q=*/TT, /*nqblocks=*/TS / QPB, /*n0k=*/0, /*nk=*/MT);

    // GEMM2: out = y @ W_proj + b_proj  (27648 x 768 x 768)
    {
        dim3 grid(CDIM / BN, MROWS / BM);
        sgemm_kernel<<<grid, 256>>>(yv, Wproj, out, bproj, MROWS, CDIM, CDIM);
    }
}

// round 2
// speedup vs baseline: 3.4773x; 3.4773x over previous
#include <cuda_runtime.h>
#include <cuda_bf16.h>
#include <math.h>
#include <stdint.h>

// Problem constants (fixed shapes from setup_inputs)
#define BATCH 32
#define SEQ   864
#define CDIM  768
#define NHEAD 12
#define HDIM  64
#define TT    288   // 2*t_h*t_w
#define TS    576   // s_h*s_w
#define MT    72    // 2*((t_h+1)//2)^2
#define MS    144   // s_h*s_w/4
#define QKVN  2304  // 3*CDIM
#define MROWS (BATCH*SEQ)   // 27648

// Scratch (allocation-free: __device__ globals)
__device__ float g_qkv[(size_t)MROWS * QKVN];    // (B*N, 3C)
__device__ float g_y[(size_t)MROWS * CDIM];      // attention output (tf32-rounded)
__device__ float g_xr[(size_t)MROWS * CDIM];     // x rounded to tf32
__device__ float g_wqkvr[(size_t)CDIM * QKVN];   // W_qkv rounded
__device__ float g_wprojr[(size_t)CDIM * CDIM];  // W_proj rounded

// ---------------------------------------------------------------------------
// Elementwise round-to-nearest tf32 (unbiased; HW mma truncates, which biases)
// ---------------------------------------------------------------------------
__device__ __forceinline__ uint32_t f2tf32(float v) {
    uint32_t r;
    asm("cvt.rna.tf32.f32 %0, %1;" : "=r"(r) : "f"(v));
    return r;
}

__global__ void round_tf32_kernel(const float* __restrict__ in,
                                  float* __restrict__ out, int n4)
{
    int i = blockIdx.x * blockDim.x + threadIdx.x;
    if (i >= n4) return;
    float4 v = ((const float4*)in)[i];
    float4 o;
    o.x = __uint_as_float(f2tf32(v.x));
    o.y = __uint_as_float(f2tf32(v.y));
    o.z = __uint_as_float(f2tf32(v.z));
    o.w = __uint_as_float(f2tf32(v.w));
    ((float4*)out)[i] = o;
}

// ---------------------------------------------------------------------------
// TF32 tensor-core GEMM: C = A(MxK) @ B(KxN) [+bias]
// 128x128 block tile, BK=32, 8 warps (2x4), warp tile 64x32, mma.m16n8k8.
// cp.async double-buffered SMEM with XOR swizzles (conflict-free LDS).
// If batch_tiles > 0: row_base = (by/batch_tiles)*SEQ + (by%batch_tiles)*128
// (used to compute only the first 256 rows of each batch for k/v columns).
// ---------------------------------------------------------------------------
#define GBM 128
#define GBN 128
#define GBK 32
#define STAGE_FLOATS 8192   // A tile 4096 + B tile 4096

__device__ __forceinline__ void cp_async16(uint32_t saddr, const void* gptr) {
    asm volatile("cp.async.cg.shared.global [%0], [%1], 16;\n"
                 :: "r"(saddr), "l"(gptr));
}

__global__ __launch_bounds__(256, 2) void sgemm_tf32_kernel(
    const float* __restrict__ A, const float* __restrict__ B,
    float* __restrict__ C, const float* __restrict__ bias,
    int K, int lda, int ldb, int ldc, int batch_tiles)
{
    __shared__ float sm[2 * STAGE_FLOATS];

    const int tid = threadIdx.x;
    const int wid = tid >> 5;
    const int lane = tid & 31;
    const int gid = lane >> 2;   // groupID 0..7
    const int tig = lane & 3;    // thread in group 0..3

    const int wm = wid >> 2;     // 0..1  (64-row warp tile)
    const int wn = wid & 3;      // 0..3  (32-col warp tile)

    const int by = blockIdx.y;
    const int row_base = (batch_tiles > 0)
        ? (by / batch_tiles) * SEQ + (by % batch_tiles) * GBM
        : by * GBM;
    const int bn = blockIdx.x * GBN;

    const uint32_t smem_base = (uint32_t)__cvta_generic_to_shared(sm);

    // precomputed per-thread loader coords
    const int a_m  = tid >> 1;               // unused path; real mapping below
    (void)a_m;

    float acc[4][4][4];
#pragma unroll
    for (int mt = 0; mt < 4; mt++)
#pragma unroll
        for (int nt = 0; nt < 4; nt++)
#pragma unroll
            for (int r = 0; r < 4; r++) acc[mt][nt][r] = 0.f;

    const int nk = K / GBK;

    // ---- tile loader (cp.async) ----
    auto load_tiles = [&](int kt, int s) {
        const float* Ag = A + (size_t)row_base * lda + kt * GBK;
        const float* Bg = B + (size_t)(kt * GBK) * ldb + bn;
        const uint32_t sb = smem_base + (uint32_t)s * STAGE_FLOATS * 4;
#pragma unroll
        for (int i = 0; i < 4; i++) {
            int f = tid + 256 * i;          // 0..1023
            int m = f >> 3;                 // 0..127
            int k4 = f & 7;                 // 0..7 (float4 along k)
            int sidx = m * 32 + ((k4 * 4) ^ ((m & 7) << 2));
            cp_async16(sb + sidx * 4, Ag + (size_t)m * lda + k4 * 4);
        }
#pragma unroll
        for (int i = 0; i < 4; i++) {
            int f = tid + 256 * i;
            int kk = f >> 5;                // 0..31
            int n4 = f & 31;                // float4 along n
            int sidx = 4096 + kk * 128 + ((n4 * 4) ^ ((kk & 3) << 3));
            cp_async16(sb + sidx * 4, Bg + (size_t)kk * ldb + n4 * 4);
        }
    };

    load_tiles(0, 0);
    asm volatile("cp.async.commit_group;\n");

    for (int kt = 0; kt < nk; kt++) {
        const int s = kt & 1;
        if (kt + 1 < nk) {
            load_tiles(kt + 1, (kt + 1) & 1);
            asm volatile("cp.async.commit_group;\n");
            asm volatile("cp.async.wait_group 1;\n");
        } else {
            asm volatile("cp.async.wait_group 0;\n");
        }
        __syncthreads();

        const float* As = sm + s * STAGE_FLOATS;
        const float* Bs = As + 4096;

#pragma unroll
        for (int ks = 0; ks < 4; ks++) {
            const int kl = ks * 8 + tig;
            uint32_t af[4][4];
            uint32_t bf[4][2];
#pragma unroll
            for (int mt = 0; mt < 4; mt++) {
                const int m = wm * 64 + mt * 16 + gid;
                const int b0 = m * 32 + (kl ^ ((m & 7) << 2));
                af[mt][0] = __float_as_uint(As[b0]);
                af[mt][1] = __float_as_uint(As[b0 + 256]);        // m+8
                af[mt][2] = __float_as_uint(As[b0 ^ 4]);          // k+4
                af[mt][3] = __float_as_uint(As[(b0 + 256) ^ 4]);
            }
#pragma unroll
            for (int nt = 0; nt < 4; nt++) {
                const int n = wn * 32 + nt * 8 + gid;
                const int b0 = kl * 128 + (n ^ ((kl & 3) << 3));
                bf[nt][0] = __float_as_uint(Bs[b0]);
                bf[nt][1] = __float_as_uint(Bs[b0 + 512]);        // k+4
            }
#pragma unroll
            for (int mt = 0; mt < 4; mt++)
#pragma unroll
                for (int nt = 0; nt < 4; nt++) {
                    asm volatile(
                        "mma.sync.aligned.m16n8k8.row.col.f32.tf32.tf32.f32 "
                        "{%0,%1,%2,%3}, {%4,%5,%6,%7}, {%8,%9}, {%0,%1,%2,%3};\n"
                        : "+f"(acc[mt][nt][0]), "+f"(acc[mt][nt][1]),
                          "+f"(acc[mt][nt][2]), "+f"(acc[mt][nt][3])
                        : "r"(af[mt][0]), "r"(af[mt][1]),
                          "r"(af[mt][2]), "r"(af[mt][3]),
                          "r"(bf[nt][0]), "r"(bf[nt][1]));
                }
        }
        __syncthreads();
    }

    // ---- epilogue ----
#pragma unroll
    for (int mt = 0; mt < 4; mt++) {
        const int row = row_base + wm * 64 + mt * 16 + gid;
#pragma unroll
        for (int nt = 0; nt < 4; nt++) {
            const int col = bn + wn * 32 + nt * 8 + tig * 2;
            float b0 = 0.f, b1 = 0.f;
            if (bias) { b0 = bias[col]; b1 = bias[col + 1]; }
            float2 v0 = make_float2(acc[mt][nt][0] + b0, acc[mt][nt][1] + b1);
            float2 v1 = make_float2(acc[mt][nt][2] + b0, acc[mt][nt][3] + b1);
            *(float2*)&C[(size_t)row * ldc + col] = v0;
            *(float2*)&C[(size_t)(row + 8) * ldc + col] = v1;
        }
    }
}

// ---------------------------------------------------------------------------
// Flash-style attention (fp32). One block = 96 queries of one (b, h).
// Writes tf32-rounded output so GEMM2 consumes pre-rounded A.
// ---------------------------------------------------------------------------
#define QPB 96

__global__ __launch_bounds__(QPB) void attn_kernel(
    const float* __restrict__ qkv, float* __restrict__ y,
    int n0q, int nqblocks, int n0k, int nk)
{
    extern __shared__ float smattn[];
    float* sK = smattn;
    float* sV = smattn + (size_t)nk * HDIM;

    const int qb = blockIdx.x % nqblocks;
    const int bh = blockIdx.x / nqblocks;
    const int b = bh / NHEAD;
    const int h = bh % NHEAD;

    const float* base = qkv + (size_t)b * SEQ * QKVN + h * HDIM;

    for (int idx = threadIdx.x; idx < nk * HDIM; idx += QPB) {
        const int r = idx >> 6;
        const int c = idx & 63;
        sK[idx] = base[(size_t)(n0k + r) * QKVN + CDIM + c];
        sV[idx] = base[(size_t)(n0k + r) * QKVN + 2 * CDIM + c];
    }
    __syncthreads();

    const int iq = qb * QPB + threadIdx.x;
    const float* qp = base + (size_t)(n0q + iq) * QKVN;

    float q[HDIM], o[HDIM];
#pragma unroll
    for (int i = 0; i < HDIM; i += 4) {
        float4 t = *(const float4*)&qp[i];
        q[i + 0] = t.x; q[i + 1] = t.y; q[i + 2] = t.z; q[i + 3] = t.w;
    }
#pragma unroll
    for (int i = 0; i < HDIM; i++) o[i] = 0.f;

    float m = -1e30f, l = 0.f;
    const float scale = 0.125f;

    for (int j = 0; j < nk; j++) {
        const float* kj = &sK[j * HDIM];
        float s = 0.f;
#pragma unroll
        for (int i = 0; i < HDIM; i += 4) {
            float4 kv = *(const float4*)&kj[i];
            s = fmaf(q[i + 0], kv.x, s);
            s = fmaf(q[i + 1], kv.y, s);
            s = fmaf(q[i + 2], kv.z, s);
            s = fmaf(q[i + 3], kv.w, s);
        }
        s *= scale;
        const float nm = fmaxf(m, s);
        const float corr = __expf(m - nm);
        const float p = __expf(s - nm);
        l = l * corr + p;
        const float* vj = &sV[j * HDIM];
#pragma unroll
        for (int i = 0; i < HDIM; i += 4) {
            float4 vv = *(const float4*)&vj[i];
            o[i + 0] = fmaf(o[i + 0], corr, p * vv.x);
            o[i + 1] = fmaf(o[i + 1], corr, p * vv.y);
            o[i + 2] = fmaf(o[i + 2], corr, p * vv.z);
            o[i + 3] = fmaf(o[i + 3], corr, p * vv.w);
        }
        m = nm;
    }

    const float inv = 1.f / l;
    float* yp = y + (size_t)(b * SEQ + n0q + iq) * CDIM + h * HDIM;
#pragma unroll
    for (int i = 0; i < HDIM; i += 4) {
        float4 v;
        v.x = __uint_as_float(f2tf32(o[i + 0] * inv));
        v.y = __uint_as_float(f2tf32(o[i + 1] * inv));
        v.z = __uint_as_float(f2tf32(o[i + 2] * inv));
        v.w = __uint_as_float(f2tf32(o[i + 3] * inv));
        *(float4*)&yp[i] = v;
    }
}

// ---------------------------------------------------------------------------
// Launch: round(x, Wqkv, Wproj) -> GEMM1(q) -> GEMM1(kv, 256 rows/batch)
//         -> attn A -> attn B -> GEMM2(+bias)
// ---------------------------------------------------------------------------
extern "C" void kernel_launch(void* const* d_in, const int* in_sizes, int n_in,
                              void* d_out, int out_size)
{
    const float* x     = (const float*)d_in[0];
    const float* Wqkv  = (const float*)d_in[1];
    const float* Wproj = (const float*)d_in[2];
    const float* bproj = (const float*)d_in[3];
    float* out = (float*)d_out;

    void *p_qkv, *p_y, *p_xr, *p_wqkvr, *p_wprojr;
    cudaGetSymbolAddress(&p_qkv, g_qkv);
    cudaGetSymbolAddress(&p_y, g_y);
    cudaGetSymbolAddress(&p_xr, g_xr);
    cudaGetSymbolAddress(&p_wqkvr, g_wqkvr);
    cudaGetSymbolAddress(&p_wprojr, g_wprojr);
    float* qkv = (float*)p_qkv;
    float* yv = (float*)p_y;
    float* xr = (float*)p_xr;
    float* wqkvr = (float*)p_wqkvr;
    float* wprojr = (float*)p_wprojr;

    const int smemA = 2 * MS * HDIM * (int)sizeof(float);
    const int smemB = 2 * MT * HDIM * (int)sizeof(float);
    cudaFuncSetAttribute(attn_kernel,
                         cudaFuncAttributeMaxDynamicSharedMemorySize, smemA);

    // ---- tf32 pre-rounding (unbiased) ----
    {
        int n4 = MROWS * CDIM / 4;
        round_tf32_kernel<<<(n4 + 255) / 256, 256>>>(x, xr, n4);
        n4 = CDIM * QKVN / 4;
        round_tf32_kernel<<<(n4 + 255) / 256, 256>>>(Wqkv, wqkvr, n4);
        n4 = CDIM * CDIM / 4;
        round_tf32_kernel<<<(n4 + 255) / 256, 256>>>(Wproj, wprojr, n4);
    }

    // ---- GEMM1a: q columns (N=768) for all rows ----
    {
        dim3 grid(CDIM / GBN, MROWS / GBM);   // (6, 216)
        sgemm_tf32_kernel<<<grid, 256>>>(xr, wqkvr, qkv, nullptr,
                                         CDIM, CDIM, QKVN, QKVN, 0);
    }
    // ---- GEMM1b: k,v columns (N=1536) for first 256 rows of each batch ----
    {
        dim3 grid(2 * CDIM / GBN, BATCH * 2); // (12, 64)
        sgemm_tf32_kernel<<<grid, 256>>>(xr, wqkvr + CDIM, qkv + CDIM, nullptr,
                                         CDIM, CDIM, QKVN, QKVN, 2);
    }

    // ---- attention ----
    attn_kernel<<<BATCH * NHEAD * (TT / QPB), QPB, smemA>>>(
        qkv, yv, 0, TT / QPB, MT, MS);
    attn_kernel<<<BATCH * NHEAD * (TS / QPB), QPB, smemB>>>(
        qkv, yv, TT, TS / QPB, 0, MT);

    // ---- GEMM2: out = y @ W_proj + b_proj ----
    {
        dim3 grid(CDIM / GBN, MROWS / GBM);   // (6, 216)
        sgemm_tf32_kernel<<<grid, 256>>>(yv, wprojr, out, bproj,
                                         CDIM, CDIM, CDIM, CDIM, 0);
    }
}

// round 3
// speedup vs baseline: 3.6997x; 1.0640x over previous
#include <cuda_runtime.h>
#include <cuda_bf16.h>
#include <math.h>
#include <stdint.h>

// Problem constants (fixed shapes from setup_inputs)
#define BATCH 32
#define SEQ   864
#define CDIM  768
#define NHEAD 12
#define HDIM  64
#define TT    288   // 2*t_h*t_w
#define TS    576   // s_h*s_w
#define MT    72    // 2*((t_h+1)//2)^2
#define MS    144   // s_h*s_w/4
#define QKVN  2304  // 3*CDIM
#define MROWS (BATCH*SEQ)   // 27648

// Scratch (allocation-free: __device__ globals)
__device__ float g_qkv[(size_t)MROWS * QKVN];    // (B*N, 3C)
__device__ float g_y[(size_t)MROWS * CDIM];      // attention output (tf32-rounded)
__device__ float g_xr[(size_t)MROWS * CDIM];     // x rounded to tf32
__device__ float g_wqkvr[(size_t)CDIM * QKVN];   // W_qkv rounded
__device__ float g_wprojr[(size_t)CDIM * CDIM];  // W_proj rounded

// ---------------------------------------------------------------------------
// Elementwise round-to-nearest tf32 (unbiased; HW mma truncates, which biases)
// ---------------------------------------------------------------------------
__device__ __forceinline__ uint32_t f2tf32(float v) {
    uint32_t r;
    asm("cvt.rna.tf32.f32 %0, %1;" : "=r"(r) : "f"(v));
    return r;
}

__global__ void round_tf32_kernel(const float* __restrict__ in,
                                  float* __restrict__ out, int n4)
{
    int i = blockIdx.x * blockDim.x + threadIdx.x;
    if (i >= n4) return;
    float4 v = ((const float4*)in)[i];
    float4 o;
    o.x = __uint_as_float(f2tf32(v.x));
    o.y = __uint_as_float(f2tf32(v.y));
    o.z = __uint_as_float(f2tf32(v.z));
    o.w = __uint_as_float(f2tf32(v.w));
    ((float4*)out)[i] = o;
}

// ---------------------------------------------------------------------------
// FMA-pipe exp: e^s = 2^(s*log2e), magic-number rint + deg-5 poly + exp add.
// No MUFU. Accurate to ~2.4e-6 rel. Valid for |s| <= ~87 (clamped to 80).
// ---------------------------------------------------------------------------
__device__ __forceinline__ float fexp(float s) {
    s = fminf(fmaxf(s, -80.f), 80.f);
    const float t = s * 1.4426950408889634f;
    const float z = t + 12582912.f;                 // 2^23 + 2^22 magic
    const int   i = __float_as_int(z) - 0x4B400000; // round-to-nearest int
    const float f = t - (z - 12582912.f);           // frac in [-0.5, 0.5]
    float p = 0.0013333558f;
    p = fmaf(p, f, 0.0096181291f);
    p = fmaf(p, f, 0.0555041087f);
    p = fmaf(p, f, 0.2402265070f);
    p = fmaf(p, f, 0.6931471806f);
    p = fmaf(p, f, 1.0f);
    return __int_as_float(__float_as_int(p) + (i << 23));
}

// ---------------------------------------------------------------------------
// TF32 tensor-core GEMM: C = A(MxK) @ B(KxN) [+bias]
// 128x128 block tile, BK=32, 8 warps (2x4), warp tile 64x32, mma.m16n8k8.
// cp.async 3-stage pipelined dynamic SMEM with XOR swizzles.
// If batch_tiles > 0: row_base = (by/batch_tiles)*SEQ + (by%batch_tiles)*128.
// ---------------------------------------------------------------------------
#define GBM 128
#define GBN 128
#define GBK 32
#define STAGE_FLOATS 8192   // A tile 4096 + B tile 4096
#define NSTAGE 3

__device__ __forceinline__ void cp_async16(uint32_t saddr, const void* gptr) {
    asm volatile("cp.async.cg.shared.global [%0], [%1], 16;\n"
                 :: "r"(saddr), "l"(gptr));
}

__global__ __launch_bounds__(256, 2) void sgemm_tf32_kernel(
    const float* __restrict__ A, const float* __restrict__ B,
    float* __restrict__ C, const float* __restrict__ bias,
    int K, int lda, int ldb, int ldc, int batch_tiles)
{
    extern __shared__ float smg[];

    const int tid = threadIdx.x;
    const int wid = tid >> 5;
    const int lane = tid & 31;
    const int gid = lane >> 2;   // groupID 0..7
    const int tig = lane & 3;    // thread in group 0..3

    const int wm = wid >> 2;     // 0..1  (64-row warp tile)
    const int wn = wid & 3;      // 0..3  (32-col warp tile)

    const int by = blockIdx.y;
    const int row_base = (batch_tiles > 0)
        ? (by / batch_tiles) * SEQ + (by % batch_tiles) * GBM
        : by * GBM;
    const int bn = blockIdx.x * GBN;

    const uint32_t smem_base = (uint32_t)__cvta_generic_to_shared(smg);

    float acc[4][4][4];
#pragma unroll
    for (int mt = 0; mt < 4; mt++)
#pragma unroll
        for (int nt = 0; nt < 4; nt++)
#pragma unroll
            for (int r = 0; r < 4; r++) acc[mt][nt][r] = 0.f;

    const int nk = K / GBK;

    auto load_tiles = [&](int kt, int s) {
        const float* Ag = A + (size_t)row_base * lda + kt * GBK;
        const float* Bg = B + (size_t)(kt * GBK) * ldb + bn;
        const uint32_t sb = smem_base + (uint32_t)s * STAGE_FLOATS * 4;
#pragma unroll
        for (int i = 0; i < 4; i++) {
            int f = tid + 256 * i;          // 0..1023
            int m = f >> 3;                 // 0..127
            int k4 = f & 7;                 // float4 along k
            int sidx = m * 32 + ((k4 * 4) ^ ((m & 7) << 2));
            cp_async16(sb + sidx * 4, Ag + (size_t)m * lda + k4 * 4);
        }
#pragma unroll
        for (int i = 0; i < 4; i++) {
            int f = tid + 256 * i;
            int kk = f >> 5;                // 0..31
            int n4 = f & 31;                // float4 along n
            int sidx = 4096 + kk * 128 + ((n4 * 4) ^ ((kk & 3) << 3));
            cp_async16(sb + sidx * 4, Bg + (size_t)kk * ldb + n4 * 4);
        }
    };

    load_tiles(0, 0);
    asm volatile("cp.async.commit_group;\n");
    load_tiles(1, 1);
    asm volatile("cp.async.commit_group;\n");

    for (int kt = 0; kt < nk; kt++) {
        const int s = kt % NSTAGE;
        if (kt + 2 < nk) {
            load_tiles(kt + 2, (kt + 2) % NSTAGE);
            asm volatile("cp.async.commit_group;\n");
            asm volatile("cp.async.wait_group 2;\n");
        } else if (kt + 1 < nk) {
            asm volatile("cp.async.wait_group 1;\n");
        } else {
            asm volatile("cp.async.wait_group 0;\n");
        }
        __syncthreads();

        const float* As = smg + s * STAGE_FLOATS;
        const float* Bs = As + 4096;

#pragma unroll
        for (int ks = 0; ks < 4; ks++) {
            const int kl = ks * 8 + tig;
            uint32_t af[4][4];
            uint32_t bf[4][2];
#pragma unroll
            for (int mt = 0; mt < 4; mt++) {
                const int m = wm * 64 + mt * 16 + gid;
                const int b0 = m * 32 + (kl ^ ((m & 7) << 2));
                af[mt][0] = __float_as_uint(As[b0]);
                af[mt][1] = __float_as_uint(As[b0 + 256]);        // m+8
                af[mt][2] = __float_as_uint(As[b0 ^ 4]);          // k+4
                af[mt][3] = __float_as_uint(As[(b0 + 256) ^ 4]);
            }
#pragma unroll
            for (int nt = 0; nt < 4; nt++) {
                const int n = wn * 32 + nt * 8 + gid;
                const int b0 = kl * 128 + (n ^ ((kl & 3) << 3));
                bf[nt][0] = __float_as_uint(Bs[b0]);
                bf[nt][1] = __float_as_uint(Bs[b0 + 512]);        // k+4
            }
#pragma unroll
            for (int mt = 0; mt < 4; mt++)
#pragma unroll
                for (int nt = 0; nt < 4; nt++) {
                    asm volatile(
                        "mma.sync.aligned.m16n8k8.row.col.f32.tf32.tf32.f32 "
                        "{%0,%1,%2,%3}, {%4,%5,%6,%7}, {%8,%9}, {%0,%1,%2,%3};\n"
                        : "+f"(acc[mt][nt][0]), "+f"(acc[mt][nt][1]),
                          "+f"(acc[mt][nt][2]), "+f"(acc[mt][nt][3])
                        : "r"(af[mt][0]), "r"(af[mt][1]),
                          "r"(af[mt][2]), "r"(af[mt][3]),
                          "r"(bf[nt][0]), "r"(bf[nt][1]));
                }
        }
        __syncthreads();
    }

    // ---- epilogue ----
#pragma unroll
    for (int mt = 0; mt < 4; mt++) {
        const int row = row_base + wm * 64 + mt * 16 + gid;
#pragma unroll
        for (int nt = 0; nt < 4; nt++) {
            const int col = bn + wn * 32 + nt * 8 + tig * 2;
            float b0 = 0.f, b1 = 0.f;
            if (bias) { b0 = bias[col]; b1 = bias[col + 1]; }
            float2 v0 = make_float2(acc[mt][nt][0] + b0, acc[mt][nt][1] + b1);
            float2 v1 = make_float2(acc[mt][nt][2] + b0, acc[mt][nt][3] + b1);
            *(float2*)&C[(size_t)row * ldc + col] = v0;
            *(float2*)&C[(size_t)(row + 8) * ldc + col] = v1;
        }
    }
}

// ---------------------------------------------------------------------------
// Flash-style attention, single-pass softmax WITHOUT running max.
// Scores here are ~N(0, 0.3): exp never overflows (clamped +-80 for safety);
// softmax without max-subtraction is mathematically identical.
// One block = 96 queries of one (b, h). 1 poly-exp (FMA pipe) per key.
// ---------------------------------------------------------------------------
#define QPB 96

__global__ __launch_bounds__(QPB) void attn_kernel(
    const float* __restrict__ qkv, float* __restrict__ y,
    int n0q, int nqblocks, int n0k, int nk)
{
    extern __shared__ float smattn[];
    float* sK = smattn;
    float* sV = smattn + (size_t)nk * HDIM;

    const int qb = blockIdx.x % nqblocks;
    const int bh = blockIdx.x / nqblocks;
    const int b = bh / NHEAD;
    const int h = bh % NHEAD;

    const float* base = qkv + (size_t)b * SEQ * QKVN + h * HDIM;

    for (int idx = threadIdx.x; idx < nk * HDIM; idx += QPB) {
        const int r = idx >> 6;
        const int c = idx & 63;
        sK[idx] = base[(size_t)(n0k + r) * QKVN + CDIM + c];
        sV[idx] = base[(size_t)(n0k + r) * QKVN + 2 * CDIM + c];
    }
    __syncthreads();

    const int iq = qb * QPB + threadIdx.x;
    const float* qp = base + (size_t)(n0q + iq) * QKVN;

    float q[HDIM], o[HDIM];
#pragma unroll
    for (int i = 0; i < HDIM; i += 4) {
        float4 t = *(const float4*)&qp[i];
        q[i + 0] = t.x * 0.125f;  // fold scale into q
        q[i + 1] = t.y * 0.125f;
        q[i + 2] = t.z * 0.125f;
        q[i + 3] = t.w * 0.125f;
    }
#pragma unroll
    for (int i = 0; i < HDIM; i++) o[i] = 0.f;

    float l = 0.f;

    for (int j = 0; j < nk; j++) {
        const float* kj = &sK[j * HDIM];
        float s = 0.f;
#pragma unroll
        for (int i = 0; i < HDIM; i += 4) {
            float4 kv = *(const float4*)&kj[i];
            s = fmaf(q[i + 0], kv.x, s);
            s = fmaf(q[i + 1], kv.y, s);
            s = fmaf(q[i + 2], kv.z, s);
            s = fmaf(q[i + 3], kv.w, s);
        }
        const float p = fexp(s);
        l += p;
        const float* vj = &sV[j * HDIM];
#pragma unroll
        for (int i = 0; i < HDIM; i += 4) {
            float4 vv = *(const float4*)&vj[i];
            o[i + 0] = fmaf(p, vv.x, o[i + 0]);
            o[i + 1] = fmaf(p, vv.y, o[i + 1]);
            o[i + 2] = fmaf(p, vv.z, o[i + 2]);
            o[i + 3] = fmaf(p, vv.w, o[i + 3]);
        }
    }

    const float inv = 1.f / l;
    float* yp = y + (size_t)(b * SEQ + n0q + iq) * CDIM + h * HDIM;
#pragma unroll
    for (int i = 0; i < HDIM; i += 4) {
        float4 v;
        v.x = __uint_as_float(f2tf32(o[i + 0] * inv));
        v.y = __uint_as_float(f2tf32(o[i + 1] * inv));
        v.z = __uint_as_float(f2tf32(o[i + 2] * inv));
        v.w = __uint_as_float(f2tf32(o[i + 3] * inv));
        *(float4*)&yp[i] = v;
    }
}

// ---------------------------------------------------------------------------
// Launch
// ---------------------------------------------------------------------------
extern "C" void kernel_launch(void* const* d_in, const int* in_sizes, int n_in,
                              void* d_out, int out_size)
{
    const float* x     = (const float*)d_in[0];
    const float* Wqkv  = (const float*)d_in[1];
    const float* Wproj = (const float*)d_in[2];
    const float* bproj = (const float*)d_in[3];
    float* out = (float*)d_out;

    void *p_qkv, *p_y, *p_xr, *p_wqkvr, *p_wprojr;
    cudaGetSymbolAddress(&p_qkv, g_qkv);
    cudaGetSymbolAddress(&p_y, g_y);
    cudaGetSymbolAddress(&p_xr, g_xr);
    cudaGetSymbolAddress(&p_wqkvr, g_wqkvr);
    cudaGetSymbolAddress(&p_wprojr, g_wprojr);
    float* qkv = (float*)p_qkv;
    float* yv = (float*)p_y;
    float* xr = (float*)p_xr;
    float* wqkvr = (float*)p_wqkvr;
    float* wprojr = (float*)p_wprojr;

    const int smemA = 2 * MS * HDIM * (int)sizeof(float);
    const int smemB = 2 * MT * HDIM * (int)sizeof(float);
    cudaFuncSetAttribute(attn_kernel,
                         cudaFuncAttributeMaxDynamicSharedMemorySize, smemA);

    const int smemG = NSTAGE * STAGE_FLOATS * (int)sizeof(float);  // 96 KB
    cudaFuncSetAttribute(sgemm_tf32_kernel,
                         cudaFuncAttributeMaxDynamicSharedMemorySize, smemG);

    // ---- tf32 pre-rounding (unbiased) ----
    {
        int n4 = MROWS * CDIM / 4;
        round_tf32_kernel<<<(n4 + 255) / 256, 256>>>(x, xr, n4);
        n4 = CDIM * QKVN / 4;
        round_tf32_kernel<<<(n4 + 255) / 256, 256>>>(Wqkv, wqkvr, n4);
        n4 = CDIM * CDIM / 4;
        round_tf32_kernel<<<(n4 + 255) / 256, 256>>>(Wproj, wprojr, n4);
    }

    // ---- GEMM1a: q columns (N=768) for all rows ----
    {
        dim3 grid(CDIM / GBN, MROWS / GBM);   // (6, 216)
        sgemm_tf32_kernel<<<grid, 256, smemG>>>(xr, wqkvr, qkv, nullptr,
                                                CDIM, CDIM, QKVN, QKVN, 0);
    }
    // ---- GEMM1b: k,v columns (N=1536) for first 256 rows of each batch ----
    {
        dim3 grid(2 * CDIM / GBN, BATCH * 2); // (12, 64)
        sgemm_tf32_kernel<<<grid, 256, smemG>>>(xr, wqkvr + CDIM, qkv + CDIM,
                                                nullptr, CDIM, CDIM, QKVN,
                                                QKVN, 2);
    }

    // ---- attention ----
    attn_kernel<<<BATCH * NHEAD * (TT / QPB), QPB, smemA>>>(
        qkv, yv, 0, TT / QPB, MT, MS);
    attn_kernel<<<BATCH * NHEAD * (TS / QPB), QPB, smemB>>>(
        qkv, yv, TT, TS / QPB, 0, MT);

    // ---- GEMM2: out = y @ W_proj + b_proj ----
    {
        dim3 grid(CDIM / GBN, MROWS / GBM);   // (6, 216)
        sgemm_tf32_kernel<<<grid, 256, smemG>>>(yv, wprojr, out, bproj,
                                                CDIM, CDIM, CDIM, CDIM, 0);
    }
}

// round 4
// speedup vs baseline: 5.5726x; 1.5062x over previous
#include <cuda_runtime.h>
#include <cuda_bf16.h>
#include <math.h>
#include <stdint.h>

// Problem constants (fixed shapes from setup_inputs)
#define BATCH 32
#define SEQ   864
#define CDIM  768
#define NHEAD 12
#define HDIM  64
#define TT    288   // 2*t_h*t_w
#define TS    576   // s_h*s_w
#define MT    72    // 2*((t_h+1)//2)^2
#define MS    144   // s_h*s_w/4
#define QKVN  2304  // 3*CDIM
#define MROWS (BATCH*SEQ)   // 27648

// Scratch (allocation-free: __device__ globals)
__device__ float g_qkv[(size_t)MROWS * QKVN];
__device__ float g_y[(size_t)MROWS * CDIM];
__device__ float g_xr[(size_t)MROWS * CDIM];
__device__ float g_wqkvr[(size_t)CDIM * QKVN];
__device__ float g_wprojr[(size_t)CDIM * CDIM];

// ---------------------------------------------------------------------------
__device__ __forceinline__ uint32_t f2tf32(float v) {
    uint32_t r;
    asm("cvt.rna.tf32.f32 %0, %1;" : "=r"(r) : "f"(v));
    return r;
}

__global__ void round_tf32_kernel(const float* __restrict__ in,
                                  float* __restrict__ out, int n4)
{
    int i = blockIdx.x * blockDim.x + threadIdx.x;
    if (i >= n4) return;
    float4 v = ((const float4*)in)[i];
    float4 o;
    o.x = __uint_as_float(f2tf32(v.x));
    o.y = __uint_as_float(f2tf32(v.y));
    o.z = __uint_as_float(f2tf32(v.z));
    o.w = __uint_as_float(f2tf32(v.w));
    ((float4*)out)[i] = o;
}

// FMA-pipe exp (no MUFU), ~2.4e-6 rel accuracy
__device__ __forceinline__ float fexp(float s) {
    s = fminf(fmaxf(s, -80.f), 80.f);
    const float t = s * 1.4426950408889634f;
    const float z = t + 12582912.f;
    const int   i = __float_as_int(z) - 0x4B400000;
    const float f = t - (z - 12582912.f);
    float p = 0.0013333558f;
    p = fmaf(p, f, 0.0096181291f);
    p = fmaf(p, f, 0.0555041087f);
    p = fmaf(p, f, 0.2402265070f);
    p = fmaf(p, f, 0.6931471806f);
    p = fmaf(p, f, 1.0f);
    return __int_as_float(__float_as_int(p) + (i << 23));
}

// ---------------------------------------------------------------------------
// TF32 GEMM: 128x128 block, BK=32, 4 warps (2x2), warp tile 64x64.
// (64x64 warp tiles halve LDS crossbar traffic vs 64x32 -> tensor pipe fed.)
// ---------------------------------------------------------------------------
#define GBM 128
#define GBN 128
#define GBK 32
#define STAGE_FLOATS 8192
#define NSTAGE 3

__device__ __forceinline__ void cp_async16(uint32_t saddr, const void* gptr) {
    asm volatile("cp.async.cg.shared.global [%0], [%1], 16;\n"
                 :: "r"(saddr), "l"(gptr));
}

__global__ __launch_bounds__(128, 2) void sgemm_tf32_kernel(
    const float* __restrict__ A, const float* __restrict__ B,
    float* __restrict__ C, const float* __restrict__ bias,
    int K, int lda, int ldb, int ldc, int batch_tiles)
{
    extern __shared__ float smg[];

    const int tid = threadIdx.x;
    const int wid = tid >> 5;
    const int lane = tid & 31;
    const int gid = lane >> 2;
    const int tig = lane & 3;

    const int wm = wid >> 1;     // 0..1 (64-row warp tile)
    const int wn = wid & 1;      // 0..1 (64-col warp tile)

    const int by = blockIdx.y;
    const int row_base = (batch_tiles > 0)
        ? (by / batch_tiles) * SEQ + (by % batch_tiles) * GBM
        : by * GBM;
    const int bn = blockIdx.x * GBN;

    const uint32_t smem_base = (uint32_t)__cvta_generic_to_shared(smg);

    float acc[4][8][4];
#pragma unroll
    for (int mt = 0; mt < 4; mt++)
#pragma unroll
        for (int nt = 0; nt < 8; nt++)
#pragma unroll
            for (int r = 0; r < 4; r++) acc[mt][nt][r] = 0.f;

    const int nk = K / GBK;

    auto load_tiles = [&](int kt, int s) {
        const float* Ag = A + (size_t)row_base * lda + kt * GBK;
        const float* Bg = B + (size_t)(kt * GBK) * ldb + bn;
        const uint32_t sb = smem_base + (uint32_t)s * STAGE_FLOATS * 4;
#pragma unroll
        for (int i = 0; i < 8; i++) {
            int f = tid + 128 * i;          // 0..1023
            int m = f >> 3;
            int k4 = f & 7;
            int sidx = m * 32 + ((k4 * 4) ^ ((m & 7) << 2));
            cp_async16(sb + sidx * 4, Ag + (size_t)m * lda + k4 * 4);
        }
#pragma unroll
        for (int i = 0; i < 8; i++) {
            int f = tid + 128 * i;
            int kk = f >> 5;
            int n4 = f & 31;
            int sidx = 4096 + kk * 128 + ((n4 * 4) ^ ((kk & 3) << 3));
            cp_async16(sb + sidx * 4, Bg + (size_t)kk * ldb + n4 * 4);
        }
    };

    load_tiles(0, 0);
    asm volatile("cp.async.commit_group;\n");
    load_tiles(1, 1);
    asm volatile("cp.async.commit_group;\n");

    for (int kt = 0; kt < nk; kt++) {
        const int s = kt % NSTAGE;
        if (kt + 2 < nk) {
            load_tiles(kt + 2, (kt + 2) % NSTAGE);
            asm volatile("cp.async.commit_group;\n");
            asm volatile("cp.async.wait_group 2;\n");
        } else if (kt + 1 < nk) {
            asm volatile("cp.async.wait_group 1;\n");
        } else {
            asm volatile("cp.async.wait_group 0;\n");
        }
        __syncthreads();

        const float* As = smg + s * STAGE_FLOATS;
        const float* Bs = As + 4096;

#pragma unroll
        for (int ks = 0; ks < 4; ks++) {
            const int kl = ks * 8 + tig;
            uint32_t af[4][4];
            uint32_t bf[8][2];
#pragma unroll
            for (int mt = 0; mt < 4; mt++) {
                const int m = wm * 64 + mt * 16 + gid;
                const int b0 = m * 32 + (kl ^ ((m & 7) << 2));
                af[mt][0] = __float_as_uint(As[b0]);
                af[mt][1] = __float_as_uint(As[b0 + 256]);
                af[mt][2] = __float_as_uint(As[b0 ^ 4]);
                af[mt][3] = __float_as_uint(As[(b0 + 256) ^ 4]);
            }
#pragma unroll
            for (int nt = 0; nt < 8; nt++) {
                const int n = wn * 64 + nt * 8 + gid;
                const int b0 = kl * 128 + (n ^ ((kl & 3) << 3));
                bf[nt][0] = __float_as_uint(Bs[b0]);
                bf[nt][1] = __float_as_uint(Bs[b0 + 512]);
            }
#pragma unroll
            for (int mt = 0; mt < 4; mt++)
#pragma unroll
                for (int nt = 0; nt < 8; nt++) {
                    asm volatile(
                        "mma.sync.aligned.m16n8k8.row.col.f32.tf32.tf32.f32 "
                        "{%0,%1,%2,%3}, {%4,%5,%6,%7}, {%8,%9}, {%0,%1,%2,%3};\n"
                        : "+f"(acc[mt][nt][0]), "+f"(acc[mt][nt][1]),
                          "+f"(acc[mt][nt][2]), "+f"(acc[mt][nt][3])
                        : "r"(af[mt][0]), "r"(af[mt][1]),
                          "r"(af[mt][2]), "r"(af[mt][3]),
                          "r"(bf[nt][0]), "r"(bf[nt][1]));
                }
        }
        __syncthreads();
    }

#pragma unroll
    for (int mt = 0; mt < 4; mt++) {
        const int row = row_base + wm * 64 + mt * 16 + gid;
#pragma unroll
        for (int nt = 0; nt < 8; nt++) {
            const int col = bn + wn * 64 + nt * 8 + tig * 2;
            float b0 = 0.f, b1 = 0.f;
            if (bias) { b0 = bias[col]; b1 = bias[col + 1]; }
            float2 v0 = make_float2(acc[mt][nt][0] + b0, acc[mt][nt][1] + b1);
            float2 v1 = make_float2(acc[mt][nt][2] + b0, acc[mt][nt][3] + b1);
            *(float2*)&C[(size_t)row * ldc + col] = v0;
            *(float2*)&C[(size_t)(row + 8) * ldc + col] = v1;
        }
    }
}

// ---------------------------------------------------------------------------
// Tensor-core attention. Block = 96 queries of one (b,h); 6 warps x 16 rows.
// S = (Q*scale)@K^T via tf32 mma (full S in fragments), no-max softmax
// (scores sigma~0.31; clamp in fexp guards), normalized P staged in SMEM
// (aliases dead Q/K region), then O = P@V via mma. Output tf32-rounded.
//   SMEM strides: Q/K/V rows padded to 72 (conflict-free fragment LDS),
//   P rows padded to NK+4.
// ---------------------------------------------------------------------------
#define KVS 72   // HDIM+8 row stride for Q/K/V in smem

template <int NK>
__global__ __launch_bounds__(192, 2) void attn_mma_kernel(
    const float* __restrict__ qkv, float* __restrict__ y,
    int n0q, int nqblocks, int n0k)
{
    constexpr int NT = NK / 8;        // S col tiles (18 or 9)
    constexpr int PSTR = NK + 4;      // P row stride
    constexpr int OFF_K = 96 * KVS;               // Q: [0, OFF_K)
    constexpr int OFF_V = OFF_K + NK * KVS;       // K: [OFF_K, OFF_V)

    extern __shared__ float sma[];
    float* sQ = sma;
    float* sK = sma + OFF_K;
    float* sV = sma + OFF_V;
    float* sP = sma;                  // aliases Q+K after QK phase

    const int tid = threadIdx.x;
    const int wid = tid >> 5;         // 0..5
    const int lane = tid & 31;
    const int gid = lane >> 2;
    const int tig = lane & 3;

    const int qb = blockIdx.x % nqblocks;
    const int bh = blockIdx.x / nqblocks;
    const int b = bh / NHEAD;
    const int h = bh % NHEAD;

    const float* base = qkv + (size_t)b * SEQ * QKVN + h * HDIM;
    const int q0 = n0q + qb * 96;

    // ---- cooperative loads (float4) ----
#pragma unroll
    for (int i = 0; i < 8; i++) {                 // Q: 96*16 f4
        int idx = tid + 192 * i;
        int r = idx >> 4, c4 = idx & 15;
        float4 v = *(const float4*)&base[(size_t)(q0 + r) * QKVN + c4 * 4];
        v.x *= 0.125f; v.y *= 0.125f; v.z *= 0.125f; v.w *= 0.125f;
        *(float4*)&sQ[r * KVS + c4 * 4] = v;
    }
#pragma unroll
    for (int i = 0; i < NK / 12; i++) {           // K: NK*16 f4
        int idx = tid + 192 * i;
        int r = idx >> 4, c4 = idx & 15;
        *(float4*)&sK[r * KVS + c4 * 4] =
            *(const float4*)&base[(size_t)(n0k + r) * QKVN + CDIM + c4 * 4];
    }
#pragma unroll
    for (int i = 0; i < NK / 12; i++) {           // V
        int idx = tid + 192 * i;
        int r = idx >> 4, c4 = idx & 15;
        *(float4*)&sV[r * KVS + c4 * 4] =
            *(const float4*)&base[(size_t)(n0k + r) * QKVN + 2 * CDIM + c4 * 4];
    }
    __syncthreads();

    const int row0 = wid * 16 + gid;

    // ---- S = Q @ K^T ----
    float acc[NT][4];
#pragma unroll
    for (int nt = 0; nt < NT; nt++)
#pragma unroll
        for (int r = 0; r < 4; r++) acc[nt][r] = 0.f;

#pragma unroll
    for (int ks = 0; ks < 8; ks++) {
        const int kl = ks * 8 + tig;
        uint32_t a0 = __float_as_uint(sQ[row0 * KVS + kl]);
        uint32_t a1 = __float_as_uint(sQ[(row0 + 8) * KVS + kl]);
        uint32_t a2 = __float_as_uint(sQ[row0 * KVS + kl + 4]);
        uint32_t a3 = __float_as_uint(sQ[(row0 + 8) * KVS + kl + 4]);
#pragma unroll
        for (int nt = 0; nt < NT; nt++) {
            const int n = nt * 8 + gid;
            uint32_t b0 = __float_as_uint(sK[n * KVS + kl]);
            uint32_t b1 = __float_as_uint(sK[n * KVS + kl + 4]);
            asm volatile(
                "mma.sync.aligned.m16n8k8.row.col.f32.tf32.tf32.f32 "
                "{%0,%1,%2,%3}, {%4,%5,%6,%7}, {%8,%9}, {%0,%1,%2,%3};\n"
                : "+f"(acc[nt][0]), "+f"(acc[nt][1]),
                  "+f"(acc[nt][2]), "+f"(acc[nt][3])
                : "r"(a0), "r"(a1), "r"(a2), "r"(a3), "r"(b0), "r"(b1));
        }
    }

    // ---- softmax (no max subtraction) ----
    float l0 = 0.f, l1 = 0.f;
#pragma unroll
    for (int nt = 0; nt < NT; nt++) {
        acc[nt][0] = fexp(acc[nt][0]);
        acc[nt][1] = fexp(acc[nt][1]);
        acc[nt][2] = fexp(acc[nt][2]);
        acc[nt][3] = fexp(acc[nt][3]);
        l0 += acc[nt][0] + acc[nt][1];
        l1 += acc[nt][2] + acc[nt][3];
    }
    l0 += __shfl_xor_sync(0xffffffff, l0, 1);
    l0 += __shfl_xor_sync(0xffffffff, l0, 2);
    l1 += __shfl_xor_sync(0xffffffff, l1, 1);
    l1 += __shfl_xor_sync(0xffffffff, l1, 2);
    const float inv0 = 1.f / l0;
    const float inv1 = 1.f / l1;

    __syncthreads();   // everyone done reading Q/K

    // ---- write normalized P (tf32-rounded: it's an mma A operand) ----
#pragma unroll
    for (int nt = 0; nt < NT; nt++) {
        const int col = nt * 8 + tig * 2;
        sP[row0 * PSTR + col]           = __uint_as_float(f2tf32(acc[nt][0] * inv0));
        sP[row0 * PSTR + col + 1]       = __uint_as_float(f2tf32(acc[nt][1] * inv0));
        sP[(row0 + 8) * PSTR + col]     = __uint_as_float(f2tf32(acc[nt][2] * inv1));
        sP[(row0 + 8) * PSTR + col + 1] = __uint_as_float(f2tf32(acc[nt][3] * inv1));
    }
    __syncthreads();

    // ---- O = P @ V ----
    float o[8][4];
#pragma unroll
    for (int nt = 0; nt < 8; nt++)
#pragma unroll
        for (int r = 0; r < 4; r++) o[nt][r] = 0.f;

#pragma unroll
    for (int ks = 0; ks < NT; ks++) {
        const int kl = ks * 8 + tig;
        uint32_t a0 = __float_as_uint(sP[row0 * PSTR + kl]);
        uint32_t a1 = __float_as_uint(sP[(row0 + 8) * PSTR + kl]);
        uint32_t a2 = __float_as_uint(sP[row0 * PSTR + kl + 4]);
        uint32_t a3 = __float_as_uint(sP[(row0 + 8) * PSTR + kl + 4]);
#pragma unroll
        for (int nt = 0; nt < 8; nt++) {
            const int n = nt * 8 + gid;
            uint32_t b0 = __float_as_uint(sV[kl * KVS + n]);
            uint32_t b1 = __float_as_uint(sV[(kl + 4) * KVS + n]);
            asm volatile(
                "mma.sync.aligned.m16n8k8.row.col.f32.tf32.tf32.f32 "
                "{%0,%1,%2,%3}, {%4,%5,%6,%7}, {%8,%9}, {%0,%1,%2,%3};\n"
                : "+f"(o[nt][0]), "+f"(o[nt][1]),
                  "+f"(o[nt][2]), "+f"(o[nt][3])
                : "r"(a0), "r"(a1), "r"(a2), "r"(a3), "r"(b0), "r"(b1));
        }
    }

    // ---- write y (tf32-rounded; consumed as GEMM2's A) ----
    float* yp = y + (size_t)(b * SEQ + q0 + row0) * CDIM + h * HDIM;
#pragma unroll
    for (int nt = 0; nt < 8; nt++) {
        const int col = nt * 8 + tig * 2;
        float2 v0, v1;
        v0.x = __uint_as_float(f2tf32(o[nt][0]));
        v0.y = __uint_as_float(f2tf32(o[nt][1]));
        v1.x = __uint_as_float(f2tf32(o[nt][2]));
        v1.y = __uint_as_float(f2tf32(o[nt][3]));
        *(float2*)&yp[col] = v0;
        *(float2*)&yp[8 * CDIM + col] = v1;
    }
}

// ---------------------------------------------------------------------------
extern "C" void kernel_launch(void* const* d_in, const int* in_sizes, int n_in,
                              void* d_out, int out_size)
{
    const float* x     = (const float*)d_in[0];
    const float* Wqkv  = (const float*)d_in[1];
    const float* Wproj = (const float*)d_in[2];
    const float* bproj = (const float*)d_in[3];
    float* out = (float*)d_out;

    void *p_qkv, *p_y, *p_xr, *p_wqkvr, *p_wprojr;
    cudaGetSymbolAddress(&p_qkv, g_qkv);
    cudaGetSymbolAddress(&p_y, g_y);
    cudaGetSymbolAddress(&p_xr, g_xr);
    cudaGetSymbolAddress(&p_wqkvr, g_wqkvr);
    cudaGetSymbolAddress(&p_wprojr, g_wprojr);
    float* qkv = (float*)p_qkv;
    float* yv = (float*)p_y;
    float* xr = (float*)p_xr;
    float* wqkvr = (float*)p_wqkvr;
    float* wprojr = (float*)p_wprojr;

    const int smemG = NSTAGE * STAGE_FLOATS * (int)sizeof(float);  // 96 KB
    cudaFuncSetAttribute(sgemm_tf32_kernel,
                         cudaFuncAttributeMaxDynamicSharedMemorySize, smemG);

    const int smemAttnA = (96 * KVS + 2 * MS * KVS) * (int)sizeof(float); // 110592
    const int smemAttnB = (96 * KVS + 2 * MT * KVS) * (int)sizeof(float); // 69120
    cudaFuncSetAttribute(attn_mma_kernel<MS>,
                         cudaFuncAttributeMaxDynamicSharedMemorySize, smemAttnA);
    cudaFuncSetAttribute(attn_mma_kernel<MT>,
                         cudaFuncAttributeMaxDynamicSharedMemorySize, smemAttnB);

    // ---- tf32 pre-rounding (unbiased) ----
    {
        int n4 = MROWS * CDIM / 4;
        round_tf32_kernel<<<(n4 + 255) / 256, 256>>>(x, xr, n4);
        n4 = CDIM * QKVN / 4;
        round_tf32_kernel<<<(n4 + 255) / 256, 256>>>(Wqkv, wqkvr, n4);
        n4 = CDIM * CDIM / 4;
        round_tf32_kernel<<<(n4 + 255) / 256, 256>>>(Wproj, wprojr, n4);
    }

    // ---- GEMM1a: q columns (N=768), all rows ----
    {
        dim3 grid(CDIM / GBN, MROWS / GBM);   // (6, 216)
        sgemm_tf32_kernel<<<grid, 128, smemG>>>(xr, wqkvr, qkv, nullptr,
                                                CDIM, CDIM, QKVN, QKVN, 0);
    }
    // ---- GEMM1b: k,v columns (N=1536), first 256 rows of each batch ----
    {
        dim3 grid(2 * CDIM / GBN, BATCH * 2); // (12, 64)
        sgemm_tf32_kernel<<<grid, 128, smemG>>>(xr, wqkvr + CDIM, qkv + CDIM,
                                                nullptr, CDIM, CDIM, QKVN,
                                                QKVN, 2);
    }

    // ---- attention (tensor-core) ----
    attn_mma_kernel<MS><<<BATCH * NHEAD * (TT / 96), 192, smemAttnA>>>(
        qkv, yv, 0, TT / 96, MT);
    attn_mma_kernel<MT><<<BATCH * NHEAD * (TS / 96), 192, smemAttnB>>>(
        qkv, yv, TT, TS / 96, 0);

    // ---- GEMM2: out = y @ W_proj + b_proj ----
    {
        dim3 grid(CDIM / GBN, MROWS / GBM);   // (6, 216)
        sgemm_tf32_kernel<<<grid, 128, smemG>>>(yv, wprojr, out, bproj,
                                                CDIM, CDIM, CDIM, CDIM, 0);
    }
}

// round 5
// speedup vs baseline: 8.6379x; 1.5501x over previous
#include <cuda_runtime.h>
#include <cuda_fp16.h>
#include <cuda_bf16.h>
#include <math.h>
#include <stdint.h>

// Problem constants (fixed shapes from setup_inputs)
#define BATCH 32
#define SEQ   864
#define CDIM  768
#define NHEAD 12
#define HDIM  64
#define TT    288   // 2*t_h*t_w
#define TS    576   // s_h*s_w
#define MT    72    // 2*((t_h+1)//2)^2
#define MS    144   // s_h*s_w/4
#define QKVN  2304  // 3*CDIM
#define MROWS (BATCH*SEQ)   // 27648

// Scratch (allocation-free: __device__ globals)
__device__ float  g_qkv[(size_t)MROWS * QKVN];     // f32 qkv (attention input)
__device__ __half g_yh[(size_t)MROWS * CDIM];      // attention out, fp16
__device__ __half g_xh[(size_t)MROWS * CDIM];      // x rounded to fp16
__device__ __half g_wqkvh[(size_t)CDIM * QKVN];    // W_qkv fp16
__device__ __half g_wprojh[(size_t)CDIM * CDIM];   // W_proj fp16

// ---------------------------------------------------------------------------
__device__ __forceinline__ uint32_t f2tf32(float v) {
    uint32_t r;
    asm("cvt.rna.tf32.f32 %0, %1;" : "=r"(r) : "f"(v));
    return r;
}

// f32 -> f16 round-to-nearest (unbiased), float4 -> 4 halves
__global__ void round_f16_kernel(const float* __restrict__ in,
                                 __half* __restrict__ out, int n4)
{
    int i = blockIdx.x * blockDim.x + threadIdx.x;
    if (i >= n4) return;
    float4 v = ((const float4*)in)[i];
    __half2 h0 = __floats2half2_rn(v.x, v.y);
    __half2 h1 = __floats2half2_rn(v.z, v.w);
    uint2 o;
    o.x = *(uint32_t*)&h0;
    o.y = *(uint32_t*)&h1;
    ((uint2*)out)[i] = o;
}

// FMA-pipe exp (no MUFU), ~2.4e-6 rel accuracy
__device__ __forceinline__ float fexp(float s) {
    s = fminf(fmaxf(s, -80.f), 80.f);
    const float t = s * 1.4426950408889634f;
    const float z = t + 12582912.f;
    const int   i = __float_as_int(z) - 0x4B400000;
    const float f = t - (z - 12582912.f);
    float p = 0.0013333558f;
    p = fmaf(p, f, 0.0096181291f);
    p = fmaf(p, f, 0.0555041087f);
    p = fmaf(p, f, 0.2402265070f);
    p = fmaf(p, f, 0.6931471806f);
    p = fmaf(p, f, 1.0f);
    return __int_as_float(__float_as_int(p) + (i << 23));
}

// ---------------------------------------------------------------------------
// FP16 tensor-core GEMM (f32 accumulate): C = A(MxK) @ B(KxN) [+bias]
// 128x128 block, BK=32, 4 warps (2x2), warp tile 64x64, mma.m16n8k16.
// ldmatrix fragment loads from chunk-XOR-swizzled SMEM (conflict-free).
// A smem: chunk(m,kc) = m*4 + (kc ^ ((m>>1)&3));  kc = k/8 in [0,4)
// B smem: chunk(k,nc) = k*16 + (nc ^ (k&7));      nc = n/8 in [0,16)
// ---------------------------------------------------------------------------
#define GBM 128
#define GBN 128
#define GBK 32
#define STAGE_BYTES 16384     // A 8KB + B 8KB
#define NSTAGE 3

__device__ __forceinline__ void cp_async16(uint32_t saddr, const void* gptr) {
    asm volatile("cp.async.cg.shared.global [%0], [%1], 16;\n"
                 :: "r"(saddr), "l"(gptr));
}

__global__ __launch_bounds__(128, 2) void hgemm_kernel(
    const __half* __restrict__ A, const __half* __restrict__ B,
    float* __restrict__ C, const float* __restrict__ bias,
    int K, int lda, int ldb, int ldc, int batch_tiles)
{
    extern __shared__ char smg[];

    const int tid = threadIdx.x;
    const int wid = tid >> 5;
    const int lane = tid & 31;
    const int gid = lane >> 2;
    const int tig = lane & 3;

    const int wm = wid >> 1;     // 0..1 (64-row warp tile)
    const int wn = wid & 1;      // 0..1 (64-col warp tile)

    const int by = blockIdx.y;
    const int row_base = (batch_tiles > 0)
        ? (by / batch_tiles) * SEQ + (by % batch_tiles) * GBM
        : by * GBM;
    const int bn = blockIdx.x * GBN;

    const uint32_t smem_base = (uint32_t)__cvta_generic_to_shared(smg);

    float acc[4][8][4];
#pragma unroll
    for (int mt = 0; mt < 4; mt++)
#pragma unroll
        for (int nt = 0; nt < 8; nt++)
#pragma unroll
            for (int r = 0; r < 4; r++) acc[mt][nt][r] = 0.f;

    const int nk = K / GBK;

    auto load_tiles = [&](int kt, int s) {
        const __half* Ag = A + (size_t)row_base * lda + kt * GBK;
        const __half* Bg = B + (size_t)(kt * GBK) * ldb + bn;
        const uint32_t sb = smem_base + (uint32_t)s * STAGE_BYTES;
        // A: 128 rows x 4 chunks of 8 halves
#pragma unroll
        for (int i = 0; i < 4; i++) {
            int f = tid + 128 * i;          // 0..511
            int m = f >> 2;
            int kc = f & 3;
            int chunk = m * 4 + (kc ^ ((m >> 1) & 3));
            cp_async16(sb + chunk * 16, Ag + (size_t)m * lda + kc * 8);
        }
        // B: 32 rows x 16 chunks of 8 halves
#pragma unroll
        for (int i = 0; i < 4; i++) {
            int f = tid + 128 * i;
            int k = f >> 4;
            int nc = f & 15;
            int chunk = k * 16 + (nc ^ (k & 7));
            cp_async16(sb + 8192 + chunk * 16, Bg + (size_t)k * ldb + nc * 8);
        }
    };

    load_tiles(0, 0);
    asm volatile("cp.async.commit_group;\n");
    load_tiles(1, 1);
    asm volatile("cp.async.commit_group;\n");

    for (int kt = 0; kt < nk; kt++) {
        const int s = kt % NSTAGE;
        if (kt + 2 < nk) {
            load_tiles(kt + 2, (kt + 2) % NSTAGE);
            asm volatile("cp.async.commit_group;\n");
            asm volatile("cp.async.wait_group 2;\n");
        } else if (kt + 1 < nk) {
            asm volatile("cp.async.wait_group 1;\n");
        } else {
            asm volatile("cp.async.wait_group 0;\n");
        }
        __syncthreads();

        const uint32_t sA = smem_base + (uint32_t)s * STAGE_BYTES;
        const uint32_t sB = sA + 8192;

#pragma unroll
        for (int ks = 0; ks < 2; ks++) {
            uint32_t af[4][4];
            uint32_t bf[8][2];
#pragma unroll
            for (int mt = 0; mt < 4; mt++) {
                const int mr = wm * 64 + mt * 16 + (lane & 15);
                const int kc = 2 * ks + (lane >> 4);
                const uint32_t addr =
                    sA + (uint32_t)(mr * 4 + (kc ^ ((mr >> 1) & 3))) * 16;
                asm volatile(
                    "ldmatrix.sync.aligned.m8n8.x4.shared.b16 "
                    "{%0,%1,%2,%3}, [%4];\n"
                    : "=r"(af[mt][0]), "=r"(af[mt][1]),
                      "=r"(af[mt][2]), "=r"(af[mt][3])
                    : "r"(addr));
            }
#pragma unroll
            for (int nt = 0; nt < 8; nt++) {
                const int kr = ks * 16 + (lane & 15);
                const int nc0 = wn * 8 + nt;
                const uint32_t addr =
                    sB + (uint32_t)(kr * 16 + (nc0 ^ (kr & 7))) * 16;
                asm volatile(
                    "ldmatrix.sync.aligned.m8n8.x2.trans.shared.b16 "
                    "{%0,%1}, [%2];\n"
                    : "=r"(bf[nt][0]), "=r"(bf[nt][1])
                    : "r"(addr));
            }
#pragma unroll
            for (int mt = 0; mt < 4; mt++)
#pragma unroll
                for (int nt = 0; nt < 8; nt++) {
                    asm volatile(
                        "mma.sync.aligned.m16n8k16.row.col.f32.f16.f16.f32 "
                        "{%0,%1,%2,%3}, {%4,%5,%6,%7}, {%8,%9}, {%0,%1,%2,%3};\n"
                        : "+f"(acc[mt][nt][0]), "+f"(acc[mt][nt][1]),
                          "+f"(acc[mt][nt][2]), "+f"(acc[mt][nt][3])
                        : "r"(af[mt][0]), "r"(af[mt][1]),
                          "r"(af[mt][2]), "r"(af[mt][3]),
                          "r"(bf[nt][0]), "r"(bf[nt][1]));
                }
        }
        __syncthreads();
    }

#pragma unroll
    for (int mt = 0; mt < 4; mt++) {
        const int row = row_base + wm * 64 + mt * 16 + gid;
#pragma unroll
        for (int nt = 0; nt < 8; nt++) {
            const int col = bn + wn * 64 + nt * 8 + tig * 2;
            float b0 = 0.f, b1 = 0.f;
            if (bias) { b0 = bias[col]; b1 = bias[col + 1]; }
            float2 v0 = make_float2(acc[mt][nt][0] + b0, acc[mt][nt][1] + b1);
            float2 v1 = make_float2(acc[mt][nt][2] + b0, acc[mt][nt][3] + b1);
            *(float2*)&C[(size_t)row * ldc + col] = v0;
            *(float2*)&C[(size_t)(row + 8) * ldc + col] = v1;
        }
    }
}

// ---------------------------------------------------------------------------
// Tensor-core attention (tf32 path, unchanged from R4 except fp16 y output).
// Block = 96 queries of one (b,h); 6 warps x 16 rows.
// ---------------------------------------------------------------------------
#define KVS 72   // HDIM+8 row stride for Q/K/V in smem

template <int NK>
__global__ __launch_bounds__(192, 2) void attn_mma_kernel(
    const float* __restrict__ qkv, __half* __restrict__ y,
    int n0q, int nqblocks, int n0k)
{
    constexpr int NT = NK / 8;
    constexpr int PSTR = NK + 4;
    constexpr int OFF_K = 96 * KVS;
    constexpr int OFF_V = OFF_K + NK * KVS;

    extern __shared__ float sma[];
    float* sQ = sma;
    float* sK = sma + OFF_K;
    float* sV = sma + OFF_V;
    float* sP = sma;

    const int tid = threadIdx.x;
    const int wid = tid >> 5;
    const int lane = tid & 31;
    const int gid = lane >> 2;
    const int tig = lane & 3;

    const int qb = blockIdx.x % nqblocks;
    const int bh = blockIdx.x / nqblocks;
    const int b = bh / NHEAD;
    const int h = bh % NHEAD;

    const float* base = qkv + (size_t)b * SEQ * QKVN + h * HDIM;
    const int q0 = n0q + qb * 96;

#pragma unroll
    for (int i = 0; i < 8; i++) {
        int idx = tid + 192 * i;
        int r = idx >> 4, c4 = idx & 15;
        float4 v = *(const float4*)&base[(size_t)(q0 + r) * QKVN + c4 * 4];
        v.x *= 0.125f; v.y *= 0.125f; v.z *= 0.125f; v.w *= 0.125f;
        *(float4*)&sQ[r * KVS + c4 * 4] = v;
    }
#pragma unroll
    for (int i = 0; i < NK / 12; i++) {
        int idx = tid + 192 * i;
        int r = idx >> 4, c4 = idx & 15;
        *(float4*)&sK[r * KVS + c4 * 4] =
            *(const float4*)&base[(size_t)(n0k + r) * QKVN + CDIM + c4 * 4];
    }
#pragma unroll
    for (int i = 0; i < NK / 12; i++) {
        int idx = tid + 192 * i;
        int r = idx >> 4, c4 = idx & 15;
        *(float4*)&sV[r * KVS + c4 * 4] =
            *(const float4*)&base[(size_t)(n0k + r) * QKVN + 2 * CDIM + c4 * 4];
    }
    __syncthreads();

    const int row0 = wid * 16 + gid;

    float acc[NT][4];
#pragma unroll
    for (int nt = 0; nt < NT; nt++)
#pragma unroll
        for (int r = 0; r < 4; r++) acc[nt][r] = 0.f;

#pragma unroll
    for (int ks = 0; ks < 8; ks++) {
        const int kl = ks * 8 + tig;
        uint32_t a0 = __float_as_uint(sQ[row0 * KVS + kl]);
        uint32_t a1 = __float_as_uint(sQ[(row0 + 8) * KVS + kl]);
        uint32_t a2 = __float_as_uint(sQ[row0 * KVS + kl + 4]);
        uint32_t a3 = __float_as_uint(sQ[(row0 + 8) * KVS + kl + 4]);
#pragma unroll
        for (int nt = 0; nt < NT; nt++) {
            const int n = nt * 8 + gid;
            uint32_t b0 = __float_as_uint(sK[n * KVS + kl]);
            uint32_t b1 = __float_as_uint(sK[n * KVS + kl + 4]);
            asm volatile(
                "mma.sync.aligned.m16n8k8.row.col.f32.tf32.tf32.f32 "
                "{%0,%1,%2,%3}, {%4,%5,%6,%7}, {%8,%9}, {%0,%1,%2,%3};\n"
                : "+f"(acc[nt][0]), "+f"(acc[nt][1]),
                  "+f"(acc[nt][2]), "+f"(acc[nt][3])
                : "r"(a0), "r"(a1), "r"(a2), "r"(a3), "r"(b0), "r"(b1));
        }
    }

    float l0 = 0.f, l1 = 0.f;
#pragma unroll
    for (int nt = 0; nt < NT; nt++) {
        acc[nt][0] = fexp(acc[nt][0]);
        acc[nt][1] = fexp(acc[nt][1]);
        acc[nt][2] = fexp(acc[nt][2]);
        acc[nt][3] = fexp(acc[nt][3]);
        l0 += acc[nt][0] + acc[nt][1];
        l1 += acc[nt][2] + acc[nt][3];
    }
    l0 += __shfl_xor_sync(0xffffffff, l0, 1);
    l0 += __shfl_xor_sync(0xffffffff, l0, 2);
    l1 += __shfl_xor_sync(0xffffffff, l1, 1);
    l1 += __shfl_xor_sync(0xffffffff, l1, 2);
    const float inv0 = 1.f / l0;
    const float inv1 = 1.f / l1;

    __syncthreads();

#pragma unroll
    for (int nt = 0; nt < NT; nt++) {
        const int col = nt * 8 + tig * 2;
        sP[row0 * PSTR + col]           = __uint_as_float(f2tf32(acc[nt][0] * inv0));
        sP[row0 * PSTR + col + 1]       = __uint_as_float(f2tf32(acc[nt][1] * inv0));
        sP[(row0 + 8) * PSTR + col]     = __uint_as_float(f2tf32(acc[nt][2] * inv1));
        sP[(row0 + 8) * PSTR + col + 1] = __uint_as_float(f2tf32(acc[nt][3] * inv1));
    }
    __syncthreads();

    float o[8][4];
#pragma unroll
    for (int nt = 0; nt < 8; nt++)
#pragma unroll
        for (int r = 0; r < 4; r++) o[nt][r] = 0.f;

#pragma unroll
    for (int ks = 0; ks < NT; ks++) {
        const int kl = ks * 8 + tig;
        uint32_t a0 = __float_as_uint(sP[row0 * PSTR + kl]);
        uint32_t a1 = __float_as_uint(sP[(row0 + 8) * PSTR + kl]);
        uint32_t a2 = __float_as_uint(sP[row0 * PSTR + kl + 4]);
        uint32_t a3 = __float_as_uint(sP[(row0 + 8) * PSTR + kl + 4]);
#pragma unroll
        for (int nt = 0; nt < 8; nt++) {
            const int n = nt * 8 + gid;
            uint32_t b0 = __float_as_uint(sV[kl * KVS + n]);
            uint32_t b1 = __float_as_uint(sV[(kl + 4) * KVS + n]);
            asm volatile(
                "mma.sync.aligned.m16n8k8.row.col.f32.tf32.tf32.f32 "
                "{%0,%1,%2,%3}, {%4,%5,%6,%7}, {%8,%9}, {%0,%1,%2,%3};\n"
                : "+f"(o[nt][0]), "+f"(o[nt][1]),
                  "+f"(o[nt][2]), "+f"(o[nt][3])
                : "r"(a0), "r"(a1), "r"(a2), "r"(a3), "r"(b0), "r"(b1));
        }
    }

    // write y as fp16 (GEMM2 consumes natively; RN rounding, unbiased)
    __half* yp = y + (size_t)(b * SEQ + q0 + row0) * CDIM + h * HDIM;
#pragma unroll
    for (int nt = 0; nt < 8; nt++) {
        const int col = nt * 8 + tig * 2;
        *(__half2*)&yp[col] = __floats2half2_rn(o[nt][0], o[nt][1]);
        *(__half2*)&yp[8 * CDIM + col] = __floats2half2_rn(o[nt][2], o[nt][3]);
    }
}

// ---------------------------------------------------------------------------
extern "C" void kernel_launch(void* const* d_in, const int* in_sizes, int n_in,
                              void* d_out, int out_size)
{
    const float* x     = (const float*)d_in[0];
    const float* Wqkv  = (const float*)d_in[1];
    const float* Wproj = (const float*)d_in[2];
    const float* bproj = (const float*)d_in[3];
    float* out = (float*)d_out;

    void *p_qkv, *p_yh, *p_xh, *p_wqkvh, *p_wprojh;
    cudaGetSymbolAddress(&p_qkv, g_qkv);
    cudaGetSymbolAddress(&p_yh, g_yh);
    cudaGetSymbolAddress(&p_xh, g_xh);
    cudaGetSymbolAddress(&p_wqkvh, g_wqkvh);
    cudaGetSymbolAddress(&p_wprojh, g_wprojh);
    float*  qkv    = (float*)p_qkv;
    __half* yh     = (__half*)p_yh;
    __half* xh     = (__half*)p_xh;
    __half* wqkvh  = (__half*)p_wqkvh;
    __half* wprojh = (__half*)p_wprojh;

    const int smemG = NSTAGE * STAGE_BYTES;   // 48 KB
    cudaFuncSetAttribute(hgemm_kernel,
                         cudaFuncAttributeMaxDynamicSharedMemorySize, smemG);

    const int smemAttnA = (96 * KVS + 2 * MS * KVS) * (int)sizeof(float);
    const int smemAttnB = (96 * KVS + 2 * MT * KVS) * (int)sizeof(float);
    cudaFuncSetAttribute(attn_mma_kernel<MS>,
                         cudaFuncAttributeMaxDynamicSharedMemorySize, smemAttnA);
    cudaFuncSetAttribute(attn_mma_kernel<MT>,
                         cudaFuncAttributeMaxDynamicSharedMemorySize, smemAttnB);

    // ---- fp16 pre-rounding (RN, unbiased) ----
    {
        int n4 = MROWS * CDIM / 4;
        round_f16_kernel<<<(n4 + 255) / 256, 256>>>(x, xh, n4);
        n4 = CDIM * QKVN / 4;
        round_f16_kernel<<<(n4 + 255) / 256, 256>>>(Wqkv, wqkvh, n4);
        n4 = CDIM * CDIM / 4;
        round_f16_kernel<<<(n4 + 255) / 256, 256>>>(Wproj, wprojh, n4);
    }

    // ---- GEMM1a: q columns (N=768), all rows ----
    {
        dim3 grid(CDIM / GBN, MROWS / GBM);   // (6, 216)
        hgemm_kernel<<<grid, 128, smemG>>>(xh, wqkvh, qkv, nullptr,
                                           CDIM, CDIM, QKVN, QKVN, 0);
    }
    // ---- GEMM1b: k,v columns (N=1536), first 256 rows of each batch ----
    {
        dim3 grid(2 * CDIM / GBN, BATCH * 2); // (12, 64)
        hgemm_kernel<<<grid, 128, smemG>>>(xh, wqkvh + CDIM, qkv + CDIM,
                                           nullptr, CDIM, CDIM, QKVN,
                                           QKVN, 2);
    }

    // ---- attention (tensor-core, tf32) ----
    attn_mma_kernel<MS><<<BATCH * NHEAD * (TT / 96), 192, smemAttnA>>>(
        qkv, yh, 0, TT / 96, MT);
    attn_mma_kernel<MT><<<BATCH * NHEAD * (TS / 96), 192, smemAttnB>>>(
        qkv, yh, TT, TS / 96, 0);

    // ---- GEMM2: out = y @ W_proj + b_proj ----
    {
        dim3 grid(CDIM / GBN, MROWS / GBM);   // (6, 216)
        hgemm_kernel<<<grid, 128, smemG>>>(yh, wprojh, out, bproj,
                                           CDIM, CDIM, CDIM, CDIM, 0);
    }
}

// round 6
// speedup vs baseline: 8.6710x; 1.0038x over previous
#include <cuda_runtime.h>
#include <cuda_fp16.h>
#include <cuda_bf16.h>
#include <math.h>
#include <stdint.h>

// Problem constants (fixed shapes from setup_inputs)
#define BATCH 32
#define SEQ   864
#define CDIM  768
#define NHEAD 12
#define HDIM  64
#define TT    288   // 2*t_h*t_w
#define TS    576   // s_h*s_w
#define MT    72    // 2*((t_h+1)//2)^2
#define MS    144   // s_h*s_w/4
#define QKVN  2304  // 3*CDIM
#define MROWS (BATCH*SEQ)   // 27648

// Scratch (allocation-free: __device__ globals)
__device__ float  g_qkv[(size_t)MROWS * QKVN];     // f32 qkv (attention input)
__device__ __half g_yh[(size_t)MROWS * CDIM];      // attention out, fp16
__device__ __half g_xh[(size_t)MROWS * CDIM];      // x rounded to fp16
__device__ __half g_wqkvh[(size_t)CDIM * QKVN];    // W_qkv fp16
__device__ __half g_wprojh[(size_t)CDIM * CDIM];   // W_proj fp16

// ---------------------------------------------------------------------------
__device__ __forceinline__ uint32_t f2tf32(float v) {
    uint32_t r;
    asm("cvt.rna.tf32.f32 %0, %1;" : "=r"(r) : "f"(v));
    return r;
}

// f32 -> f16 round-to-nearest (unbiased), float4 -> 4 halves
__global__ void round_f16_kernel(const float* __restrict__ in,
                                 __half* __restrict__ out, int n4)
{
    int i = blockIdx.x * blockDim.x + threadIdx.x;
    if (i >= n4) return;
    float4 v = ((const float4*)in)[i];
    __half2 h0 = __floats2half2_rn(v.x, v.y);
    __half2 h1 = __floats2half2_rn(v.z, v.w);
    uint2 o;
    o.x = *(uint32_t*)&h0;
    o.y = *(uint32_t*)&h1;
    ((uint2*)out)[i] = o;
}

// FMA-pipe exp (no MUFU), ~2.4e-6 rel accuracy
__device__ __forceinline__ float fexp(float s) {
    s = fminf(fmaxf(s, -80.f), 80.f);
    const float t = s * 1.4426950408889634f;
    const float z = t + 12582912.f;
    const int   i = __float_as_int(z) - 0x4B400000;
    const float f = t - (z - 12582912.f);
    float p = 0.0013333558f;
    p = fmaf(p, f, 0.0096181291f);
    p = fmaf(p, f, 0.0555041087f);
    p = fmaf(p, f, 0.2402265070f);
    p = fmaf(p, f, 0.6931471806f);
    p = fmaf(p, f, 1.0f);
    return __int_as_float(__float_as_int(p) + (i << 23));
}

// ---------------------------------------------------------------------------
// FP16 tensor-core GEMM (f32 accumulate): C = A(MxK) @ B(KxN) [+bias]
// 128x128 block, BK=32, 4 warps (2x2), warp tile 64x64, mma.m16n8k16.
// ldmatrix fragment loads from chunk-XOR-swizzled SMEM (conflict-free).
// A smem: chunk(m,kc) = m*4 + (kc ^ ((m>>1)&3));  kc = k/8 in [0,4)
// B smem: chunk(k,nc) = k*16 + (nc ^ (k&7));      nc = n/8 in [0,16)
// ---------------------------------------------------------------------------
#define GBM 128
#define GBN 128
#define GBK 32
#define STAGE_BYTES 16384     // A 8KB + B 8KB
#define NSTAGE 3

__device__ __forceinline__ void cp_async16(uint32_t saddr, const void* gptr) {
    asm volatile("cp.async.cg.shared.global [%0], [%1], 16;\n"
                 :: "r"(saddr), "l"(gptr));
}

__global__ __launch_bounds__(128, 2) void hgemm_kernel(
    const __half* __restrict__ A, const __half* __restrict__ B,
    float* __restrict__ C, const float* __restrict__ bias,
    int K, int lda, int ldb, int ldc, int batch_tiles)
{
    extern __shared__ char smg[];

    const int tid = threadIdx.x;
    const int wid = tid >> 5;
    const int lane = tid & 31;
    const int gid = lane >> 2;
    const int tig = lane & 3;

    const int wm = wid >> 1;     // 0..1 (64-row warp tile)
    const int wn = wid & 1;      // 0..1 (64-col warp tile)

    const int by = blockIdx.y;
    const int row_base = (batch_tiles > 0)
        ? (by / batch_tiles) * SEQ + (by % batch_tiles) * GBM
        : by * GBM;
    const int bn = blockIdx.x * GBN;

    const uint32_t smem_base = (uint32_t)__cvta_generic_to_shared(smg);

    float acc[4][8][4];
#pragma unroll
    for (int mt = 0; mt < 4; mt++)
#pragma unroll
        for (int nt = 0; nt < 8; nt++)
#pragma unroll
            for (int r = 0; r < 4; r++) acc[mt][nt][r] = 0.f;

    const int nk = K / GBK;

    auto load_tiles = [&](int kt, int s) {
        const __half* Ag = A + (size_t)row_base * lda + kt * GBK;
        const __half* Bg = B + (size_t)(kt * GBK) * ldb + bn;
        const uint32_t sb = smem_base + (uint32_t)s * STAGE_BYTES;
        // A: 128 rows x 4 chunks of 8 halves
#pragma unroll
        for (int i = 0; i < 4; i++) {
            int f = tid + 128 * i;          // 0..511
            int m = f >> 2;
            int kc = f & 3;
            int chunk = m * 4 + (kc ^ ((m >> 1) & 3));
            cp_async16(sb + chunk * 16, Ag + (size_t)m * lda + kc * 8);
        }
        // B: 32 rows x 16 chunks of 8 halves
#pragma unroll
        for (int i = 0; i < 4; i++) {
            int f = tid + 128 * i;
            int k = f >> 4;
            int nc = f & 15;
            int chunk = k * 16 + (nc ^ (k & 7));
            cp_async16(sb + 8192 + chunk * 16, Bg + (size_t)k * ldb + nc * 8);
        }
    };

    load_tiles(0, 0);
    asm volatile("cp.async.commit_group;\n");
    load_tiles(1, 1);
    asm volatile("cp.async.commit_group;\n");

    for (int kt = 0; kt < nk; kt++) {
        const int s = kt % NSTAGE;
        if (kt + 2 < nk) {
            load_tiles(kt + 2, (kt + 2) % NSTAGE);
            asm volatile("cp.async.commit_group;\n");
            asm volatile("cp.async.wait_group 2;\n");
        } else if (kt + 1 < nk) {
            asm volatile("cp.async.wait_group 1;\n");
        } else {
            asm volatile("cp.async.wait_group 0;\n");
        }
        __syncthreads();

        const uint32_t sA = smem_base + (uint32_t)s * STAGE_BYTES;
        const uint32_t sB = sA + 8192;

#pragma unroll
        for (int ks = 0; ks < 2; ks++) {
            uint32_t af[4][4];
            uint32_t bf[8][2];
#pragma unroll
            for (int mt = 0; mt < 4; mt++) {
                const int mr = wm * 64 + mt * 16 + (lane & 15);
                const int kc = 2 * ks + (lane >> 4);
                const uint32_t addr =
                    sA + (uint32_t)(mr * 4 + (kc ^ ((mr >> 1) & 3))) * 16;
                asm volatile(
                    "ldmatrix.sync.aligned.m8n8.x4.shared.b16 "
                    "{%0,%1,%2,%3}, [%4];\n"
                    : "=r"(af[mt][0]), "=r"(af[mt][1]),
                      "=r"(af[mt][2]), "=r"(af[mt][3])
                    : "r"(addr));
            }
#pragma unroll
            for (int nt = 0; nt < 8; nt++) {
                const int kr = ks * 16 + (lane & 15);
                const int nc0 = wn * 8 + nt;
                const uint32_t addr =
                    sB + (uint32_t)(kr * 16 + (nc0 ^ (kr & 7))) * 16;
                asm volatile(
                    "ldmatrix.sync.aligned.m8n8.x2.trans.shared.b16 "
                    "{%0,%1}, [%2];\n"
                    : "=r"(bf[nt][0]), "=r"(bf[nt][1])
                    : "r"(addr));
            }
#pragma unroll
            for (int mt = 0; mt < 4; mt++)
#pragma unroll
                for (int nt = 0; nt < 8; nt++) {
                    asm volatile(
                        "mma.sync.aligned.m16n8k16.row.col.f32.f16.f16.f32 "
                        "{%0,%1,%2,%3}, {%4,%5,%6,%7}, {%8,%9}, {%0,%1,%2,%3};\n"
                        : "+f"(acc[mt][nt][0]), "+f"(acc[mt][nt][1]),
                          "+f"(acc[mt][nt][2]), "+f"(acc[mt][nt][3])
                        : "r"(af[mt][0]), "r"(af[mt][1]),
                          "r"(af[mt][2]), "r"(af[mt][3]),
                          "r"(bf[nt][0]), "r"(bf[nt][1]));
                }
        }
        __syncthreads();
    }

#pragma unroll
    for (int mt = 0; mt < 4; mt++) {
        const int row = row_base + wm * 64 + mt * 16 + gid;
#pragma unroll
        for (int nt = 0; nt < 8; nt++) {
            const int col = bn + wn * 64 + nt * 8 + tig * 2;
            float b0 = 0.f, b1 = 0.f;
            if (bias) { b0 = bias[col]; b1 = bias[col + 1]; }
            float2 v0 = make_float2(acc[mt][nt][0] + b0, acc[mt][nt][1] + b1);
            float2 v1 = make_float2(acc[mt][nt][2] + b0, acc[mt][nt][3] + b1);
            *(float2*)&C[(size_t)row * ldc + col] = v0;
            *(float2*)&C[(size_t)(row + 8) * ldc + col] = v1;
        }
    }
}

// ---------------------------------------------------------------------------
// Tensor-core attention (tf32 path, unchanged from R4 except fp16 y output).
// Block = 96 queries of one (b,h); 6 warps x 16 rows.
// ---------------------------------------------------------------------------
#define KVS 72   // HDIM+8 row stride for Q/K/V in smem

template <int NK>
__global__ __launch_bounds__(192, 2) void attn_mma_kernel(
    const float* __restrict__ qkv, __half* __restrict__ y,
    int n0q, int nqblocks, int n0k)
{
    constexpr int NT = NK / 8;
    constexpr int PSTR = NK + 4;
    constexpr int OFF_K = 96 * KVS;
    constexpr int OFF_V = OFF_K + NK * KVS;

    extern __shared__ float sma[];
    float* sQ = sma;
    float* sK = sma + OFF_K;
    float* sV = sma + OFF_V;
    float* sP = sma;

    const int tid = threadIdx.x;
    const int wid = tid >> 5;
    const int lane = tid & 31;
    const int gid = lane >> 2;
    const int tig = lane & 3;

    const int qb = blockIdx.x % nqblocks;
    const int bh = blockIdx.x / nqblocks;
    const int b = bh / NHEAD;
    const int h = bh % NHEAD;

    const float* base = qkv + (size_t)b * SEQ * QKVN + h * HDIM;
    const int q0 = n0q + qb * 96;

#pragma unroll
    for (int i = 0; i < 8; i++) {
        int idx = tid + 192 * i;
        int r = idx >> 4, c4 = idx & 15;
        float4 v = *(const float4*)&base[(size_t)(q0 + r) * QKVN + c4 * 4];
        v.x *= 0.125f; v.y *= 0.125f; v.z *= 0.125f; v.w *= 0.125f;
        *(float4*)&sQ[r * KVS + c4 * 4] = v;
    }
#pragma unroll
    for (int i = 0; i < NK / 12; i++) {
        int idx = tid + 192 * i;
        int r = idx >> 4, c4 = idx & 15;
        *(float4*)&sK[r * KVS + c4 * 4] =
            *(const float4*)&base[(size_t)(n0k + r) * QKVN + CDIM + c4 * 4];
    }
#pragma unroll
    for (int i = 0; i < NK / 12; i++) {
        int idx = tid + 192 * i;
        int r = idx >> 4, c4 = idx & 15;
        *(float4*)&sV[r * KVS + c4 * 4] =
            *(const float4*)&base[(size_t)(n0k + r) * QKVN + 2 * CDIM + c4 * 4];
    }
    __syncthreads();

    const int row0 = wid * 16 + gid;

    float acc[NT][4];
#pragma unroll
    for (int nt = 0; nt < NT; nt++)
#pragma unroll
        for (int r = 0; r < 4; r++) acc[nt][r] = 0.f;

#pragma unroll
    for (int ks = 0; ks < 8; ks++) {
        const int kl = ks * 8 + tig;
        uint32_t a0 = __float_as_uint(sQ[row0 * KVS + kl]);
        uint32_t a1 = __float_as_uint(sQ[(row0 + 8) * KVS + kl]);
        uint32_t a2 = __float_as_uint(sQ[row0 * KVS + kl + 4]);
        uint32_t a3 = __float_as_uint(sQ[(row0 + 8) * KVS + kl + 4]);
#pragma unroll
        for (int nt = 0; nt < NT; nt++) {
            const int n = nt * 8 + gid;
            uint32_t b0 = __float_as_uint(sK[n * KVS + kl]);
            uint32_t b1 = __float_as_uint(sK[n * KVS + kl + 4]);
            asm volatile(
                "mma.sync.aligned.m16n8k8.row.col.f32.tf32.tf32.f32 "
                "{%0,%1,%2,%3}, {%4,%5,%6,%7}, {%8,%9}, {%0,%1,%2,%3};\n"
                : "+f"(acc[nt][0]), "+f"(acc[nt][1]),
                  "+f"(acc[nt][2]), "+f"(acc[nt][3])
                : "r"(a0), "r"(a1), "r"(a2), "r"(a3), "r"(b0), "r"(b1));
        }
    }

    float l0 = 0.f, l1 = 0.f;
#pragma unroll
    for (int nt = 0; nt < NT; nt++) {
        acc[nt][0] = fexp(acc[nt][0]);
        acc[nt][1] = fexp(acc[nt][1]);
        acc[nt][2] = fexp(acc[nt][2]);
        acc[nt][3] = fexp(acc[nt][3]);
        l0 += acc[nt][0] + acc[nt][1];
        l1 += acc[nt][2] + acc[nt][3];
    }
    l0 += __shfl_xor_sync(0xffffffff, l0, 1);
    l0 += __shfl_xor_sync(0xffffffff, l0, 2);
    l1 += __shfl_xor_sync(0xffffffff, l1, 1);
    l1 += __shfl_xor_sync(0xffffffff, l1, 2);
    const float inv0 = 1.f / l0;
    const float inv1 = 1.f / l1;

    __syncthreads();

#pragma unroll
    for (int nt = 0; nt < NT; nt++) {
        const int col = nt * 8 + tig * 2;
        sP[row0 * PSTR + col]           = __uint_as_float(f2tf32(acc[nt][0] * inv0));
        sP[row0 * PSTR + col + 1]       = __uint_as_float(f2tf32(acc[nt][1] * inv0));
        sP[(row0 + 8) * PSTR + col]     = __uint_as_float(f2tf32(acc[nt][2] * inv1));
        sP[(row0 + 8) * PSTR + col + 1] = __uint_as_float(f2tf32(acc[nt][3] * inv1));
    }
    __syncthreads();

    float o[8][4];
#pragma unroll
    for (int nt = 0; nt < 8; nt++)
#pragma unroll
        for (int r = 0; r < 4; r++) o[nt][r] = 0.f;

#pragma unroll
    for (int ks = 0; ks < NT; ks++) {
        const int kl = ks * 8 + tig;
        uint32_t a0 = __float_as_uint(sP[row0 * PSTR + kl]);
        uint32_t a1 = __float_as_uint(sP[(row0 + 8) * PSTR + kl]);
        uint32_t a2 = __float_as_uint(sP[row0 * PSTR + kl + 4]);
        uint32_t a3 = __float_as_uint(sP[(row0 + 8) * PSTR + kl + 4]);
#pragma unroll
        for (int nt = 0; nt < 8; nt++) {
            const int n = nt * 8 + gid;
            uint32_t b0 = __float_as_uint(sV[kl * KVS + n]);
            uint32_t b1 = __float_as_uint(sV[(kl + 4) * KVS + n]);
            asm volatile(
                "mma.sync.aligned.m16n8k8.row.col.f32.tf32.tf32.f32 "
                "{%0,%1,%2,%3}, {%4,%5,%6,%7}, {%8,%9}, {%0,%1,%2,%3};\n"
                : "+f"(o[nt][0]), "+f"(o[nt][1]),
                  "+f"(o[nt][2]), "+f"(o[nt][3])
                : "r"(a0), "r"(a1), "r"(a2), "r"(a3), "r"(b0), "r"(b1));
        }
    }

    // write y as fp16 (GEMM2 consumes natively; RN rounding, unbiased)
    __half* yp = y + (size_t)(b * SEQ + q0 + row0) * CDIM + h * HDIM;
#pragma unroll
    for (int nt = 0; nt < 8; nt++) {
        const int col = nt * 8 + tig * 2;
        *(__half2*)&yp[col] = __floats2half2_rn(o[nt][0], o[nt][1]);
        *(__half2*)&yp[8 * CDIM + col] = __floats2half2_rn(o[nt][2], o[nt][3]);
    }
}

// ---------------------------------------------------------------------------
extern "C" void kernel_launch(void* const* d_in, const int* in_sizes, int n_in,
                              void* d_out, int out_size)
{
    const float* x     = (const float*)d_in[0];
    const float* Wqkv  = (const float*)d_in[1];
    const float* Wproj = (const float*)d_in[2];
    const float* bproj = (const float*)d_in[3];
    float* out = (float*)d_out;

    void *p_qkv, *p_yh, *p_xh, *p_wqkvh, *p_wprojh;
    cudaGetSymbolAddress(&p_qkv, g_qkv);
    cudaGetSymbolAddress(&p_yh, g_yh);
    cudaGetSymbolAddress(&p_xh, g_xh);
    cudaGetSymbolAddress(&p_wqkvh, g_wqkvh);
    cudaGetSymbolAddress(&p_wprojh, g_wprojh);
    float*  qkv    = (float*)p_qkv;
    __half* yh     = (__half*)p_yh;
    __half* xh     = (__half*)p_xh;
    __half* wqkvh  = (__half*)p_wqkvh;
    __half* wprojh = (__half*)p_wprojh;

    const int smemG = NSTAGE * STAGE_BYTES;   // 48 KB
    cudaFuncSetAttribute(hgemm_kernel,
                         cudaFuncAttributeMaxDynamicSharedMemorySize, smemG);

    const int smemAttnA = (96 * KVS + 2 * MS * KVS) * (int)sizeof(float);
    const int smemAttnB = (96 * KVS + 2 * MT * KVS) * (int)sizeof(float);
    cudaFuncSetAttribute(attn_mma_kernel<MS>,
                         cudaFuncAttributeMaxDynamicSharedMemorySize, smemAttnA);
    cudaFuncSetAttribute(attn_mma_kernel<MT>,
                         cudaFuncAttributeMaxDynamicSharedMemorySize, smemAttnB);

    // ---- fp16 pre-rounding (RN, unbiased) ----
    {
        int n4 = MROWS * CDIM / 4;
        round_f16_kernel<<<(n4 + 255) / 256, 256>>>(x, xh, n4);
        n4 = CDIM * QKVN / 4;
        round_f16_kernel<<<(n4 + 255) / 256, 256>>>(Wqkv, wqkvh, n4);
        n4 = CDIM * CDIM / 4;
        round_f16_kernel<<<(n4 + 255) / 256, 256>>>(Wproj, wprojh, n4);
    }

    // ---- GEMM1a: q columns (N=768), all rows ----
    {
        dim3 grid(CDIM / GBN, MROWS / GBM);   // (6, 216)
        hgemm_kernel<<<grid, 128, smemG>>>(xh, wqkvh, qkv, nullptr,
                                           CDIM, CDIM, QKVN, QKVN, 0);
    }
    // ---- GEMM1b: k,v columns (N=1536), first 256 rows of each batch ----
    {
        dim3 grid(2 * CDIM / GBN, BATCH * 2); // (12, 64)
        hgemm_kernel<<<grid, 128, smemG>>>(xh, wqkvh + CDIM, qkv + CDIM,
                                           nullptr, CDIM, CDIM, QKVN,
                                           QKVN, 2);
    }

    // ---- attention (tensor-core, tf32) ----
    attn_mma_kernel<MS><<<BATCH * NHEAD * (TT / 96), 192, smemAttnA>>>(
        qkv, yh, 0, TT / 96, MT);
    attn_mma_kernel<MT><<<BATCH * NHEAD * (TS / 96), 192, smemAttnB>>>(
        qkv, yh, TT, TS / 96, 0);

    // ---- GEMM2: out = y @ W_proj + b_proj ----
    {
        dim3 grid(CDIM / GBN, MROWS / GBM);   // (6, 216)
        hgemm_kernel<<<grid, 128, smemG>>>(yh, wprojh, out, bproj,
                                           CDIM, CDIM, CDIM, CDIM, 0);
    }
}

// round 7
// speedup vs baseline: 8.6812x; 1.0012x over previous
#include <cuda_runtime.h>
#include <cuda_fp16.h>
#include <cuda_bf16.h>
#include <math.h>
#include <stdint.h>

// Problem constants (fixed shapes from setup_inputs)
#define BATCH 32
#define SEQ   864
#define CDIM  768
#define NHEAD 12
#define HDIM  64
#define TT    288   // 2*t_h*t_w
#define TS    576   // s_h*s_w
#define MT    72    // 2*((t_h+1)//2)^2
#define MS    144   // s_h*s_w/4
#define QKVN  2304  // 3*CDIM
#define MROWS (BATCH*SEQ)   // 27648

// Scratch (allocation-free: __device__ globals)
__device__ float  g_qkv[(size_t)MROWS * QKVN];     // f32 qkv (attention input)
__device__ __half g_yh[(size_t)MROWS * CDIM];      // attention out, fp16
__device__ __half g_xh[(size_t)MROWS * CDIM];      // x rounded to fp16
__device__ __half g_wqkvh[(size_t)CDIM * QKVN];    // W_qkv fp16
__device__ __half g_wprojh[(size_t)CDIM * CDIM];   // W_proj fp16

// ---------------------------------------------------------------------------
__device__ __forceinline__ uint32_t f2tf32(float v) {
    uint32_t r;
    asm("cvt.rna.tf32.f32 %0, %1;" : "=r"(r) : "f"(v));
    return r;
}

// f32 -> f16 round-to-nearest (unbiased), float4 -> 4 halves
__global__ void round_f16_kernel(const float* __restrict__ in,
                                 __half* __restrict__ out, int n4)
{
    int i = blockIdx.x * blockDim.x + threadIdx.x;
    if (i >= n4) return;
    float4 v = ((const float4*)in)[i];
    __half2 h0 = __floats2half2_rn(v.x, v.y);
    __half2 h1 = __floats2half2_rn(v.z, v.w);
    uint2 o;
    o.x = *(uint32_t*)&h0;
    o.y = *(uint32_t*)&h1;
    ((uint2*)out)[i] = o;
}

// FMA-pipe exp (no MUFU), ~2.4e-6 rel accuracy
__device__ __forceinline__ float fexp(float s) {
    s = fminf(fmaxf(s, -80.f), 80.f);
    const float t = s * 1.4426950408889634f;
    const float z = t + 12582912.f;
    const int   i = __float_as_int(z) - 0x4B400000;
    const float f = t - (z - 12582912.f);
    float p = 0.0013333558f;
    p = fmaf(p, f, 0.0096181291f);
    p = fmaf(p, f, 0.0555041087f);
    p = fmaf(p, f, 0.2402265070f);
    p = fmaf(p, f, 0.6931471806f);
    p = fmaf(p, f, 1.0f);
    return __int_as_float(__float_as_int(p) + (i << 23));
}

// ---------------------------------------------------------------------------
// FP16 tensor-core GEMM (f32 accumulate): C = A(MxK) @ B(KxN) [+bias]
// 128x128 block, BK=32, 4 warps (2x2), warp tile 64x64, mma.m16n8k16.
// ldmatrix fragment loads from chunk-XOR-swizzled SMEM (conflict-free).
// A smem: chunk(m,kc) = m*4 + (kc ^ ((m>>1)&3));  kc = k/8 in [0,4)
// B smem: chunk(k,nc) = k*16 + (nc ^ (k&7));      nc = n/8 in [0,16)
// ---------------------------------------------------------------------------
#define GBM 128
#define GBN 128
#define GBK 32
#define STAGE_BYTES 16384     // A 8KB + B 8KB
#define NSTAGE 3

__device__ __forceinline__ void cp_async16(uint32_t saddr, const void* gptr) {
    asm volatile("cp.async.cg.shared.global [%0], [%1], 16;\n"
                 :: "r"(saddr), "l"(gptr));
}

__global__ __launch_bounds__(128, 2) void hgemm_kernel(
    const __half* __restrict__ A, const __half* __restrict__ B,
    float* __restrict__ C, const float* __restrict__ bias,
    int K, int lda, int ldb, int ldc, int batch_tiles)
{
    extern __shared__ char smg[];

    const int tid = threadIdx.x;
    const int wid = tid >> 5;
    const int lane = tid & 31;
    const int gid = lane >> 2;
    const int tig = lane & 3;

    const int wm = wid >> 1;     // 0..1 (64-row warp tile)
    const int wn = wid & 1;      // 0..1 (64-col warp tile)

    const int by = blockIdx.y;
    const int row_base = (batch_tiles > 0)
        ? (by / batch_tiles) * SEQ + (by % batch_tiles) * GBM
        : by * GBM;
    const int bn = blockIdx.x * GBN;

    const uint32_t smem_base = (uint32_t)__cvta_generic_to_shared(smg);

    float acc[4][8][4];
#pragma unroll
    for (int mt = 0; mt < 4; mt++)
#pragma unroll
        for (int nt = 0; nt < 8; nt++)
#pragma unroll
            for (int r = 0; r < 4; r++) acc[mt][nt][r] = 0.f;

    const int nk = K / GBK;

    auto load_tiles = [&](int kt, int s) {
        const __half* Ag = A + (size_t)row_base * lda + kt * GBK;
        const __half* Bg = B + (size_t)(kt * GBK) * ldb + bn;
        const uint32_t sb = smem_base + (uint32_t)s * STAGE_BYTES;
        // A: 128 rows x 4 chunks of 8 halves
#pragma unroll
        for (int i = 0; i < 4; i++) {
            int f = tid + 128 * i;          // 0..511
            int m = f >> 2;
            int kc = f & 3;
            int chunk = m * 4 + (kc ^ ((m >> 1) & 3));
            cp_async16(sb + chunk * 16, Ag + (size_t)m * lda + kc * 8);
        }
        // B: 32 rows x 16 chunks of 8 halves
#pragma unroll
        for (int i = 0; i < 4; i++) {
            int f = tid + 128 * i;
            int k = f >> 4;
            int nc = f & 15;
            int chunk = k * 16 + (nc ^ (k & 7));
            cp_async16(sb + 8192 + chunk * 16, Bg + (size_t)k * ldb + nc * 8);
        }
    };

    load_tiles(0, 0);
    asm volatile("cp.async.commit_group;\n");
    load_tiles(1, 1);
    asm volatile("cp.async.commit_group;\n");

    for (int kt = 0; kt < nk; kt++) {
        const int s = kt % NSTAGE;
        if (kt + 2 < nk) {
            load_tiles(kt + 2, (kt + 2) % NSTAGE);
            asm volatile("cp.async.commit_group;\n");
            asm volatile("cp.async.wait_group 2;\n");
        } else if (kt + 1 < nk) {
            asm volatile("cp.async.wait_group 1;\n");
        } else {
            asm volatile("cp.async.wait_group 0;\n");
        }
        __syncthreads();

        const uint32_t sA = smem_base + (uint32_t)s * STAGE_BYTES;
        const uint32_t sB = sA + 8192;

#pragma unroll
        for (int ks = 0; ks < 2; ks++) {
            uint32_t af[4][4];
            uint32_t bf[8][2];
#pragma unroll
            for (int mt = 0; mt < 4; mt++) {
                const int mr = wm * 64 + mt * 16 + (lane & 15);
                const int kc = 2 * ks + (lane >> 4);
                const uint32_t addr =
                    sA + (uint32_t)(mr * 4 + (kc ^ ((mr >> 1) & 3))) * 16;
                asm volatile(
                    "ldmatrix.sync.aligned.m8n8.x4.shared.b16 "
                    "{%0,%1,%2,%3}, [%4];\n"
                    : "=r"(af[mt][0]), "=r"(af[mt][1]),
                      "=r"(af[mt][2]), "=r"(af[mt][3])
                    : "r"(addr));
            }
#pragma unroll
            for (int nt = 0; nt < 8; nt++) {
                const int kr = ks * 16 + (lane & 15);
                const int nc0 = wn * 8 + nt;
                const uint32_t addr =
                    sB + (uint32_t)(kr * 16 + (nc0 ^ (kr & 7))) * 16;
                asm volatile(
                    "ldmatrix.sync.aligned.m8n8.x2.trans.shared.b16 "
                    "{%0,%1}, [%2];\n"
                    : "=r"(bf[nt][0]), "=r"(bf[nt][1])
                    : "r"(addr));
            }
#pragma unroll
            for (int mt = 0; mt < 4; mt++)
#pragma unroll
                for (int nt = 0; nt < 8; nt++) {
                    asm volatile(
                        "mma.sync.aligned.m16n8k16.row.col.f32.f16.f16.f32 "
                        "{%0,%1,%2,%3}, {%4,%5,%6,%7}, {%8,%9}, {%0,%1,%2,%3};\n"
                        : "+f"(acc[mt][nt][0]), "+f"(acc[mt][nt][1]),
                          "+f"(acc[mt][nt][2]), "+f"(acc[mt][nt][3])
                        : "r"(af[mt][0]), "r"(af[mt][1]),
                          "r"(af[mt][2]), "r"(af[mt][3]),
                          "r"(bf[nt][0]), "r"(bf[nt][1]));
                }
        }
        __syncthreads();
    }

#pragma unroll
    for (int mt = 0; mt < 4; mt++) {
        const int row = row_base + wm * 64 + mt * 16 + gid;
#pragma unroll
        for (int nt = 0; nt < 8; nt++) {
            const int col = bn + wn * 64 + nt * 8 + tig * 2;
            float b0 = 0.f, b1 = 0.f;
            if (bias) { b0 = bias[col]; b1 = bias[col + 1]; }
            float2 v0 = make_float2(acc[mt][nt][0] + b0, acc[mt][nt][1] + b1);
            float2 v1 = make_float2(acc[mt][nt][2] + b0, acc[mt][nt][3] + b1);
            *(float2*)&C[(size_t)row * ldc + col] = v0;
            *(float2*)&C[(size_t)(row + 8) * ldc + col] = v1;
        }
    }
}

// ---------------------------------------------------------------------------
// Tensor-core attention (tf32 path, unchanged from R4 except fp16 y output).
// Block = 96 queries of one (b,h); 6 warps x 16 rows.
// ---------------------------------------------------------------------------
#define KVS 72   // HDIM+8 row stride for Q/K/V in smem

template <int NK>
__global__ __launch_bounds__(192, 2) void attn_mma_kernel(
    const float* __restrict__ qkv, __half* __restrict__ y,
    int n0q, int nqblocks, int n0k)
{
    constexpr int NT = NK / 8;
    constexpr int PSTR = NK + 4;
    constexpr int OFF_K = 96 * KVS;
    constexpr int OFF_V = OFF_K + NK * KVS;

    extern __shared__ float sma[];
    float* sQ = sma;
    float* sK = sma + OFF_K;
    float* sV = sma + OFF_V;
    float* sP = sma;

    const int tid = threadIdx.x;
    const int wid = tid >> 5;
    const int lane = tid & 31;
    const int gid = lane >> 2;
    const int tig = lane & 3;

    const int qb = blockIdx.x % nqblocks;
    const int bh = blockIdx.x / nqblocks;
    const int b = bh / NHEAD;
    const int h = bh % NHEAD;

    const float* base = qkv + (size_t)b * SEQ * QKVN + h * HDIM;
    const int q0 = n0q + qb * 96;

#pragma unroll
    for (int i = 0; i < 8; i++) {
        int idx = tid + 192 * i;
        int r = idx >> 4, c4 = idx & 15;
        float4 v = *(const float4*)&base[(size_t)(q0 + r) * QKVN + c4 * 4];
        v.x *= 0.125f; v.y *= 0.125f; v.z *= 0.125f; v.w *= 0.125f;
        *(float4*)&sQ[r * KVS + c4 * 4] = v;
    }
#pragma unroll
    for (int i = 0; i < NK / 12; i++) {
        int idx = tid + 192 * i;
        int r = idx >> 4, c4 = idx & 15;
        *(float4*)&sK[r * KVS + c4 * 4] =
            *(const float4*)&base[(size_t)(n0k + r) * QKVN + CDIM + c4 * 4];
    }
#pragma unroll
    for (int i = 0; i < NK / 12; i++) {
        int idx = tid + 192 * i;
        int r = idx >> 4, c4 = idx & 15;
        *(float4*)&sV[r * KVS + c4 * 4] =
            *(const float4*)&base[(size_t)(n0k + r) * QKVN + 2 * CDIM + c4 * 4];
    }
    __syncthreads();

    const int row0 = wid * 16 + gid;

    float acc[NT][4];
#pragma unroll
    for (int nt = 0; nt < NT; nt++)
#pragma unroll
        for (int r = 0; r < 4; r++) acc[nt][r] = 0.f;

#pragma unroll
    for (int ks = 0; ks < 8; ks++) {
        const int kl = ks * 8 + tig;
        uint32_t a0 = __float_as_uint(sQ[row0 * KVS + kl]);
        uint32_t a1 = __float_as_uint(sQ[(row0 + 8) * KVS + kl]);
        uint32_t a2 = __float_as_uint(sQ[row0 * KVS + kl + 4]);
        uint32_t a3 = __float_as_uint(sQ[(row0 + 8) * KVS + kl + 4]);
#pragma unroll
        for (int nt = 0; nt < NT; nt++) {
            const int n = nt * 8 + gid;
            uint32_t b0 = __float_as_uint(sK[n * KVS + kl]);
            uint32_t b1 = __float_as_uint(sK[n * KVS + kl + 4]);
            asm volatile(
                "mma.sync.aligned.m16n8k8.row.col.f32.tf32.tf32.f32 "
                "{%0,%1,%2,%3}, {%4,%5,%6,%7}, {%8,%9}, {%0,%1,%2,%3};\n"
                : "+f"(acc[nt][0]), "+f"(acc[nt][1]),
                  "+f"(acc[nt][2]), "+f"(acc[nt][3])
                : "r"(a0), "r"(a1), "r"(a2), "r"(a3), "r"(b0), "r"(b1));
        }
    }

    float l0 = 0.f, l1 = 0.f;
#pragma unroll
    for (int nt = 0; nt < NT; nt++) {
        acc[nt][0] = fexp(acc[nt][0]);
        acc[nt][1] = fexp(acc[nt][1]);
        acc[nt][2] = fexp(acc[nt][2]);
        acc[nt][3] = fexp(acc[nt][3]);
        l0 += acc[nt][0] + acc[nt][1];
        l1 += acc[nt][2] + acc[nt][3];
    }
    l0 += __shfl_xor_sync(0xffffffff, l0, 1);
    l0 += __shfl_xor_sync(0xffffffff, l0, 2);
    l1 += __shfl_xor_sync(0xffffffff, l1, 1);
    l1 += __shfl_xor_sync(0xffffffff, l1, 2);
    const float inv0 = 1.f / l0;
    const float inv1 = 1.f / l1;

    __syncthreads();

#pragma unroll
    for (int nt = 0; nt < NT; nt++) {
        const int col = nt * 8 + tig * 2;
        sP[row0 * PSTR + col]           = __uint_as_float(f2tf32(acc[nt][0] * inv0));
        sP[row0 * PSTR + col + 1]       = __uint_as_float(f2tf32(acc[nt][1] * inv0));
        sP[(row0 + 8) * PSTR + col]     = __uint_as_float(f2tf32(acc[nt][2] * inv1));
        sP[(row0 + 8) * PSTR + col + 1] = __uint_as_float(f2tf32(acc[nt][3] * inv1));
    }
    __syncthreads();

    float o[8][4];
#pragma unroll
    for (int nt = 0; nt < 8; nt++)
#pragma unroll
        for (int r = 0; r < 4; r++) o[nt][r] = 0.f;

#pragma unroll
    for (int ks = 0; ks < NT; ks++) {
        const int kl = ks * 8 + tig;
        uint32_t a0 = __float_as_uint(sP[row0 * PSTR + kl]);
        uint32_t a1 = __float_as_uint(sP[(row0 + 8) * PSTR + kl]);
        uint32_t a2 = __float_as_uint(sP[row0 * PSTR + kl + 4]);
        uint32_t a3 = __float_as_uint(sP[(row0 + 8) * PSTR + kl + 4]);
#pragma unroll
        for (int nt = 0; nt < 8; nt++) {
            const int n = nt * 8 + gid;
            uint32_t b0 = __float_as_uint(sV[kl * KVS + n]);
            uint32_t b1 = __float_as_uint(sV[(kl + 4) * KVS + n]);
            asm volatile(
                "mma.sync.aligned.m16n8k8.row.col.f32.tf32.tf32.f32 "
                "{%0,%1,%2,%3}, {%4,%5,%6,%7}, {%8,%9}, {%0,%1,%2,%3};\n"
                : "+f"(o[nt][0]), "+f"(o[nt][1]),
                  "+f"(o[nt][2]), "+f"(o[nt][3])
                : "r"(a0), "r"(a1), "r"(a2), "r"(a3), "r"(b0), "r"(b1));
        }
    }

    // write y as fp16 (GEMM2 consumes natively; RN rounding, unbiased)
    __half* yp = y + (size_t)(b * SEQ + q0 + row0) * CDIM + h * HDIM;
#pragma unroll
    for (int nt = 0; nt < 8; nt++) {
        const int col = nt * 8 + tig * 2;
        *(__half2*)&yp[col] = __floats2half2_rn(o[nt][0], o[nt][1]);
        *(__half2*)&yp[8 * CDIM + col] = __floats2half2_rn(o[nt][2], o[nt][3]);
    }
}

// ---------------------------------------------------------------------------
extern "C" void kernel_launch(void* const* d_in, const int* in_sizes, int n_in,
                              void* d_out, int out_size)
{
    const float* x     = (const float*)d_in[0];
    const float* Wqkv  = (const float*)d_in[1];
    const float* Wproj = (const float*)d_in[2];
    const float* bproj = (const float*)d_in[3];
    float* out = (float*)d_out;

    void *p_qkv, *p_yh, *p_xh, *p_wqkvh, *p_wprojh;
    cudaGetSymbolAddress(&p_qkv, g_qkv);
    cudaGetSymbolAddress(&p_yh, g_yh);
    cudaGetSymbolAddress(&p_xh, g_xh);
    cudaGetSymbolAddress(&p_wqkvh, g_wqkvh);
    cudaGetSymbolAddress(&p_wprojh, g_wprojh);
    float*  qkv    = (float*)p_qkv;
    __half* yh     = (__half*)p_yh;
    __half* xh     = (__half*)p_xh;
    __half* wqkvh  = (__half*)p_wqkvh;
    __half* wprojh = (__half*)p_wprojh;

    const int smemG = NSTAGE * STAGE_BYTES;   // 48 KB
    cudaFuncSetAttribute(hgemm_kernel,
                         cudaFuncAttributeMaxDynamicSharedMemorySize, smemG);

    const int smemAttnA = (96 * KVS + 2 * MS * KVS) * (int)sizeof(float);
    const int smemAttnB = (96 * KVS + 2 * MT * KVS) * (int)sizeof(float);
    cudaFuncSetAttribute(attn_mma_kernel<MS>,
                         cudaFuncAttributeMaxDynamicSharedMemorySize, smemAttnA);
    cudaFuncSetAttribute(attn_mma_kernel<MT>,
                         cudaFuncAttributeMaxDynamicSharedMemorySize, smemAttnB);

    // ---- fp16 pre-rounding (RN, unbiased) ----
    {
        int n4 = MROWS * CDIM / 4;
        round_f16_kernel<<<(n4 + 255) / 256, 256>>>(x, xh, n4);
        n4 = CDIM * QKVN / 4;
        round_f16_kernel<<<(n4 + 255) / 256, 256>>>(Wqkv, wqkvh, n4);
        n4 = CDIM * CDIM / 4;
        round_f16_kernel<<<(n4 + 255) / 256, 256>>>(Wproj, wprojh, n4);
    }

    // ---- GEMM1a: q columns (N=768), all rows ----
    {
        dim3 grid(CDIM / GBN, MROWS / GBM);   // (6, 216)
        hgemm_kernel<<<grid, 128, smemG>>>(xh, wqkvh, qkv, nullptr,
                                           CDIM, CDIM, QKVN, QKVN, 0);
    }
    // ---- GEMM1b: k,v columns (N=1536), first 256 rows of each batch ----
    {
        dim3 grid(2 * CDIM / GBN, BATCH * 2); // (12, 64)
        hgemm_kernel<<<grid, 128, smemG>>>(xh, wqkvh + CDIM, qkv + CDIM,
                                           nullptr, CDIM, CDIM, QKVN,
                                           QKVN, 2);
    }

    // ---- attention (tensor-core, tf32) ----
    attn_mma_kernel<MS><<<BATCH * NHEAD * (TT / 96), 192, smemAttnA>>>(
        qkv, yh, 0, TT / 96, MT);
    attn_mma_kernel<MT><<<BATCH * NHEAD * (TS / 96), 192, smemAttnB>>>(
        qkv, yh, TT, TS / 96, 0);

    // ---- GEMM2: out = y @ W_proj + b_proj ----
    {
        dim3 grid(CDIM / GBN, MROWS / GBM);   // (6, 216)
        hgemm_kernel<<<grid, 128, smemG>>>(yh, wprojh, out, bproj,
                                           CDIM, CDIM, CDIM, CDIM, 0);
    }
}